// round 1
// baseline (speedup 1.0000x reference)
#include <cuda_runtime.h>
#include <cstdint>

#define BB 4
#define LL 4096
#define DD 256
#define BL (BB*LL)
#define LP1 (LL+1)
#define CH 16
#define CSZ 256

// ---------------- static scratch (no runtime allocation allowed) ----------------
__device__ float g_xT[DD*BL];           // x transposed: xT[d][m], m = b*L + l
__device__ float g_WvT[DD*DD];          // Wv transposed: WvT[d][e]
__device__ float g_V[BL*DD];            // V = x @ Wv^T
__device__ float g_uq[DD];
__device__ float g_uk[DD];
__device__ float g_qs[BL];              // q scalar (bias folded in)
__device__ float g_ks[BL];              // k scalar
__device__ float g_ksort[BL];           // per-batch sorted keys (ascending)
__device__ int   g_ord[BL];             // original index of sorted position
__device__ float g_chE[BB*CH];
__device__ float g_chEV[BB*CH*DD];
__device__ float g_chV[BB*CH*DD];
__device__ float g_PE[BB*LP1];          // exclusive prefix of e^{-k} over sorted order
__device__ float g_PEV[(size_t)BB*LP1*DD]; // exclusive prefix of e^{-k} * V[sorted]
__device__ float g_PV [(size_t)BB*LP1*DD]; // exclusive prefix of V[sorted]

// ---------------- transpose: x (16384x256) -> xT (256x16384) ----------------
__global__ void k_txx(const float* __restrict__ src) {
    __shared__ float tile[32][33];
    const int C = DD, R = BL;
    int c0 = blockIdx.x * 32, r0 = blockIdx.y * 32;
    for (int rr = threadIdx.y; rr < 32; rr += 8) {
        tile[rr][threadIdx.x] = src[(size_t)(r0 + rr) * C + c0 + threadIdx.x];
    }
    __syncthreads();
    for (int rr = threadIdx.y; rr < 32; rr += 8) {
        g_xT[(size_t)(c0 + rr) * R + r0 + threadIdx.x] = tile[threadIdx.x][rr];
    }
}

// ---------------- transpose: Wv (256x256) -> WvT (256x256) ----------------
__global__ void k_txw(const float* __restrict__ src) {
    __shared__ float tile[32][33];
    const int C = DD, R = DD;
    int c0 = blockIdx.x * 32, r0 = blockIdx.y * 32;
    for (int rr = threadIdx.y; rr < 32; rr += 8) {
        tile[rr][threadIdx.x] = src[(size_t)(r0 + rr) * C + c0 + threadIdx.x];
    }
    __syncthreads();
    for (int rr = threadIdx.y; rr < 32; rr += 8) {
        g_WvT[(size_t)(c0 + rr) * R + r0 + threadIdx.x] = tile[threadIdx.x][rr];
    }
}

// ---------------- uq = Wq^T @ w, uk = Wk^T @ w ----------------
__global__ void k_uvec(const float* __restrict__ Wq, const float* __restrict__ Wk,
                       const float* __restrict__ w) {
    int d = threadIdx.x;
    float uq = 0.f, uk = 0.f;
    for (int e = 0; e < DD; e++) {
        float we = w[e];
        uq = fmaf(Wq[e * DD + d], we, uq);
        uk = fmaf(Wk[e * DD + d], we, uk);
    }
    g_uq[d] = uq;
    g_uk[d] = uk;
}

// ---------------- per-row scalar q/k: one warp per row ----------------
__global__ void k_qk(const float* __restrict__ x, const float* __restrict__ bptr) {
    int warp = threadIdx.x >> 5, lane = threadIdx.x & 31;
    int m = blockIdx.x * 8 + warp;
    const float* xr = x + (size_t)m * DD;
    float sq = 0.f, sk = 0.f;
    #pragma unroll
    for (int d = lane; d < DD; d += 32) {
        float xv = xr[d];
        sq = fmaf(xv, g_uq[d], sq);
        sk = fmaf(xv, g_uk[d], sk);
    }
    #pragma unroll
    for (int o = 16; o; o >>= 1) {
        sq += __shfl_down_sync(0xffffffffu, sq, o);
        sk += __shfl_down_sync(0xffffffffu, sk, o);
    }
    if (lane == 0) {
        g_qs[m] = sq + bptr[0];   // fold bias into q: score = relu(q+b - k)
        g_ks[m] = sk;
    }
}

// ---------------- V = x @ Wv^T : fp32 tiled GEMM (transposed operands) ----------------
#define GBM 128
#define GBN 64
#define GBK 32
__global__ void __launch_bounds__(256) k_vgemm() {
    __shared__ float sA[GBK][GBM];
    __shared__ float sB[GBK][GBN];
    int tid = threadIdx.x;
    int tx = tid & 15, ty = tid >> 4;
    int m0 = blockIdx.x * GBM, n0 = blockIdx.y * GBN;

    float acc[8][4];
    #pragma unroll
    for (int i = 0; i < 8; i++)
        #pragma unroll
        for (int j = 0; j < 4; j++) acc[i][j] = 0.f;

    for (int k0 = 0; k0 < DD; k0 += GBK) {
        #pragma unroll
        for (int p = 0; p < 4; p++) {
            int e = p * 1024 + tid * 4;
            int kk = e >> 7, mm = e & 127;
            *(float4*)&sA[kk][mm] = *(const float4*)&g_xT[(size_t)(k0 + kk) * BL + m0 + mm];
        }
        #pragma unroll
        for (int p = 0; p < 2; p++) {
            int e = p * 1024 + tid * 4;
            int kk = e >> 6, nn = e & 63;
            *(float4*)&sB[kk][nn] = *(const float4*)&g_WvT[(k0 + kk) * DD + n0 + nn];
        }
        __syncthreads();
        #pragma unroll
        for (int k = 0; k < GBK; k++) {
            float a[8], bb[4];
            *(float4*)(a)     = *(float4*)&sA[k][ty * 8];
            *(float4*)(a + 4) = *(float4*)&sA[k][ty * 8 + 4];
            *(float4*)(bb)    = *(float4*)&sB[k][tx * 4];
            #pragma unroll
            for (int i = 0; i < 8; i++)
                #pragma unroll
                for (int j = 0; j < 4; j++)
                    acc[i][j] = fmaf(a[i], bb[j], acc[i][j]);
        }
        __syncthreads();
    }
    #pragma unroll
    for (int i = 0; i < 8; i++) {
        float4 v = make_float4(acc[i][0], acc[i][1], acc[i][2], acc[i][3]);
        *(float4*)&g_V[(size_t)(m0 + ty * 8 + i) * DD + n0 + tx * 4] = v;
    }
}

// ---------------- per-batch bitonic sort of k scalars (ascending) ----------------
__global__ void __launch_bounds__(1024) k_sort() {
    __shared__ float sk[LL];
    __shared__ int   si[LL];
    int b = blockIdx.x, tid = threadIdx.x;
    for (int i = tid; i < LL; i += 1024) { sk[i] = g_ks[b * LL + i]; si[i] = i; }
    __syncthreads();
    for (int k = 2; k <= LL; k <<= 1) {
        for (int j = k >> 1; j > 0; j >>= 1) {
            for (int i = tid; i < LL; i += 1024) {
                int ixj = i ^ j;
                if (ixj > i) {
                    bool asc = ((i & k) == 0);
                    float a = sk[i], c = sk[ixj];
                    bool doswap = asc ? (a > c) : (a < c);
                    if (doswap) {
                        sk[i] = c; sk[ixj] = a;
                        int t = si[i]; si[i] = si[ixj]; si[ixj] = t;
                    }
                }
            }
            __syncthreads();
        }
    }
    for (int i = tid; i < LL; i += 1024) {
        g_ksort[b * LL + i] = sk[i];
        g_ord[b * LL + i]   = si[i];
    }
}

// ---------------- scan phase 1: per-chunk sums ----------------
__global__ void k_chunksum() {
    int bx = blockIdx.x;
    int b = bx >> 4, c = bx & 15;
    int d = threadIdx.x;
    __shared__ float ev[CSZ];
    __shared__ float red[CSZ];
    int base = b * LL + c * CSZ;
    ev[d] = expf(-g_ksort[base + d]);
    __syncthreads();
    float sEV = 0.f, sV = 0.f;
    for (int i = 0; i < CSZ; i++) {
        int row = g_ord[base + i];
        float v = g_V[(size_t)(b * LL + row) * DD + d];
        sEV = fmaf(ev[i], v, sEV);
        sV += v;
    }
    g_chEV[(b * CH + c) * DD + d] = sEV;
    g_chV [(b * CH + c) * DD + d] = sV;
    red[d] = ev[d];
    __syncthreads();
    for (int s = 128; s; s >>= 1) {
        if (d < s) red[d] += red[d + s];
        __syncthreads();
    }
    if (d == 0) g_chE[b * CH + c] = red[0];
}

// ---------------- scan phase 2: exclusive scan over chunk sums ----------------
__global__ void k_chunkscan() {
    int b = blockIdx.x, d = threadIdx.x;
    float runEV = 0.f, runV = 0.f;
    for (int c = 0; c < CH; c++) {
        int idx = (b * CH + c) * DD + d;
        float t1 = g_chEV[idx]; g_chEV[idx] = runEV; runEV += t1;
        float t2 = g_chV[idx];  g_chV[idx]  = runV;  runV  += t2;
    }
    if (d == 0) {
        float run = 0.f;
        for (int c = 0; c < CH; c++) {
            float t = g_chE[b * CH + c]; g_chE[b * CH + c] = run; run += t;
        }
    }
}

// ---------------- scan phase 3: emit full exclusive prefixes ----------------
__global__ void k_emit() {
    int bx = blockIdx.x;
    int b = bx >> 4, c = bx & 15;
    int d = threadIdx.x;
    __shared__ float ev[CSZ];
    int base = b * LL + c * CSZ;
    ev[d] = expf(-g_ksort[base + d]);
    __syncthreads();
    float aEV = g_chEV[(b * CH + c) * DD + d];
    float aV  = g_chV [(b * CH + c) * DD + d];
    size_t pbase = ((size_t)b * LP1 + c * CSZ) * DD;
    for (int i = 0; i < CSZ; i++) {
        g_PEV[pbase + (size_t)i * DD + d] = aEV;
        g_PV [pbase + (size_t)i * DD + d] = aV;
        int row = g_ord[base + i];
        float v = g_V[(size_t)(b * LL + row) * DD + d];
        aEV = fmaf(ev[i], v, aEV);
        aV += v;
    }
    if (c == CH - 1) {
        g_PEV[((size_t)b * LP1 + LL) * DD + d] = aEV;
        g_PV [((size_t)b * LP1 + LL) * DD + d] = aV;   // = total V sum
    }
    if (d == 0) {
        float aE = g_chE[b * CH + c];
        for (int i = 0; i < CSZ; i++) {
            g_PE[b * LP1 + c * CSZ + i] = aE;
            aE += ev[i];
        }
        if (c == CH - 1) g_PE[b * LP1 + LL] = aE;
    }
}

// ---------------- final output: binary search + weighted combine ----------------
__global__ void k_out(float* __restrict__ out) {
    int bx = blockIdx.x;
    int b = bx >> 12;           // / 4096
    int d = threadIdx.x;
    float q = g_qs[bx];
    const float* ks = g_ksort + b * LL;
    // t = #{ k_j < q }  (first index with key >= q in ascending sorted array)
    int lo = 0, hi = LL;
    while (lo < hi) {
        int mid = (lo + hi) >> 1;
        if (__ldg(&ks[mid]) < q) lo = mid + 1; else hi = mid;
    }
    int t = lo;
    float E = expf(q);
    float den = fmaf(E, g_PE[b * LP1 + t], (float)(LL - t));
    size_t pidx = ((size_t)b * LP1 + t)  * DD + d;
    size_t tvix = ((size_t)b * LP1 + LL) * DD + d;
    float suffV = __ldg(&g_PV[tvix]) - g_PV[pidx];
    float num = fmaf(E, g_PEV[pidx], suffV);
    out[(size_t)bx * DD + d] = num / den;
}

// ---------------- launch ----------------
extern "C" void kernel_launch(void* const* d_in, const int* in_sizes, int n_in,
                              void* d_out, int out_size) {
    const float* x   = (const float*)d_in[0];
    const float* Wq  = (const float*)d_in[1];
    const float* Wk  = (const float*)d_in[2];
    const float* Wv  = (const float*)d_in[3];
    const float* w   = (const float*)d_in[4];
    const float* bm  = (const float*)d_in[5];
    float* out = (float*)d_out;

    k_txw<<<dim3(DD / 32, DD / 32), dim3(32, 8)>>>(Wv);
    k_txx<<<dim3(DD / 32, BL / 32), dim3(32, 8)>>>(x);
    k_uvec<<<1, DD>>>(Wq, Wk, w);
    k_qk<<<BL / 8, 256>>>(x, bm);
    k_vgemm<<<dim3(BL / GBM, DD / GBN), 256>>>();
    k_sort<<<BB, 1024>>>();
    k_chunksum<<<BB * CH, CSZ>>>();
    k_chunkscan<<<BB, DD>>>();
    k_emit<<<BB * CH, CSZ>>>();
    k_out<<<BL, DD>>>(out);
}

// round 2
// speedup vs baseline: 1.4710x; 1.4710x over previous
#include <cuda_runtime.h>
#include <cstdint>

#define BB 4
#define LL 4096
#define DD 256
#define BL (BB*LL)
#define LP1 (LL+1)
#define CH 128
#define CSZ 32

// ---------------- static scratch ----------------
__device__ float g_V[BL*DD];            // V = x @ Wv^T
__device__ float g_uq[DD];
__device__ float g_uk[DD];
__device__ float g_qs[BL];              // q scalar (bias folded in)
__device__ float g_ks[BL];              // k scalar
__device__ float g_ksort[BL];           // per-batch sorted keys (ascending)
__device__ int   g_ord[BL];             // original index at sorted position
__device__ int   g_t[BL];               // per-query threshold rank
__device__ float g_chE[BB*CH];
__device__ float g_chEV[BB*CH*DD];
__device__ float g_chV[BB*CH*DD];
__device__ float g_PE[BB*LP1];
__device__ float g_PEV[(size_t)BB*LP1*DD];
__device__ float g_PV [(size_t)BB*LP1*DD];

// ---------------- uq = Wq^T w, uk = Wk^T w (grid.x: 0->uq, 1->uk) ----------------
__global__ void __launch_bounds__(1024) k_uvec(const float* __restrict__ Wq,
                                               const float* __restrict__ Wk,
                                               const float* __restrict__ w) {
    __shared__ float part[4][DD];
    const float* W = (blockIdx.x == 0) ? Wq : Wk;
    int d = threadIdx.x & 255, ec = threadIdx.x >> 8;   // 4 chunks of 64 e
    float s = 0.f;
    #pragma unroll 8
    for (int e = ec * 64; e < ec * 64 + 64; e++)
        s = fmaf(W[e * DD + d], w[e], s);
    part[ec][d] = s;
    __syncthreads();
    if (ec == 0) {
        float r = part[0][d] + part[1][d] + part[2][d] + part[3][d];
        if (blockIdx.x == 0) g_uq[d] = r; else g_uk[d] = r;
    }
}

// ---------------- per-row scalar q/k ----------------
__global__ void __launch_bounds__(256) k_qk(const float* __restrict__ x,
                                            const float* __restrict__ bptr) {
    __shared__ float suq[DD], suk[DD];
    suq[threadIdx.x] = g_uq[threadIdx.x];
    suk[threadIdx.x] = g_uk[threadIdx.x];
    __syncthreads();
    int warp = threadIdx.x >> 5, lane = threadIdx.x & 31;
    float bias = bptr[0];
    #pragma unroll
    for (int r = 0; r < 8; r++) {
        int m = blockIdx.x * 64 + warp * 8 + r;
        const float* xr = x + (size_t)m * DD;
        float4 xa = *(const float4*)&xr[lane * 4];
        float4 xb = *(const float4*)&xr[128 + lane * 4];
        int da = lane * 4, db = 128 + lane * 4;
        float sq = xa.x * suq[da] + xa.y * suq[da+1] + xa.z * suq[da+2] + xa.w * suq[da+3]
                 + xb.x * suq[db] + xb.y * suq[db+1] + xb.z * suq[db+2] + xb.w * suq[db+3];
        float sk = xa.x * suk[da] + xa.y * suk[da+1] + xa.z * suk[da+2] + xa.w * suk[da+3]
                 + xb.x * suk[db] + xb.y * suk[db+1] + xb.z * suk[db+2] + xb.w * suk[db+3];
        #pragma unroll
        for (int o = 16; o; o >>= 1) {
            sq += __shfl_down_sync(0xffffffffu, sq, o);
            sk += __shfl_down_sync(0xffffffffu, sk, o);
        }
        if (lane == 0) { g_qs[m] = sq + bias; g_ks[m] = sk; }
    }
}

// ---------------- V = x @ Wv^T : 128x128x16 tiles, 8x8 micro ----------------
#define BM 128
#define BN 128
#define BK 16
#define APITCH (BM+4)
__global__ void __launch_bounds__(256) k_vgemm(const float* __restrict__ x,
                                               const float* __restrict__ Wv) {
    __shared__ float sA[BK][APITCH];
    __shared__ float sB[BK][APITCH];
    int tid = threadIdx.x;
    int tx = tid & 15, ty = tid >> 4;
    int m0 = blockIdx.x * BM, n0 = blockIdx.y * BN;

    float acc[8][8];
    #pragma unroll
    for (int i = 0; i < 8; i++)
        #pragma unroll
        for (int j = 0; j < 8; j++) acc[i][j] = 0.f;

    for (int k0 = 0; k0 < DD; k0 += BK) {
        #pragma unroll
        for (int p = 0; p < 2; p++) {
            int i = p * 256 + tid;
            int row = i >> 2, kq = i & 3;
            float4 v = *(const float4*)&x[(size_t)(m0 + row) * DD + k0 + kq * 4];
            sA[kq*4+0][row] = v.x; sA[kq*4+1][row] = v.y;
            sA[kq*4+2][row] = v.z; sA[kq*4+3][row] = v.w;
            float4 u = *(const float4*)&Wv[(size_t)(n0 + row) * DD + k0 + kq * 4];
            sB[kq*4+0][row] = u.x; sB[kq*4+1][row] = u.y;
            sB[kq*4+2][row] = u.z; sB[kq*4+3][row] = u.w;
        }
        __syncthreads();
        #pragma unroll
        for (int k = 0; k < BK; k++) {
            float a[8], b[8];
            *(float4*)(a)     = *(float4*)&sA[k][ty * 8];
            *(float4*)(a + 4) = *(float4*)&sA[k][ty * 8 + 4];
            *(float4*)(b)     = *(float4*)&sB[k][tx * 8];
            *(float4*)(b + 4) = *(float4*)&sB[k][tx * 8 + 4];
            #pragma unroll
            for (int i = 0; i < 8; i++)
                #pragma unroll
                for (int j = 0; j < 8; j++)
                    acc[i][j] = fmaf(a[i], b[j], acc[i][j]);
        }
        __syncthreads();
    }
    #pragma unroll
    for (int i = 0; i < 8; i++) {
        float* orow = &g_V[(size_t)(m0 + ty * 8 + i) * DD + n0 + tx * 8];
        *(float4*)(orow)     = make_float4(acc[i][0], acc[i][1], acc[i][2], acc[i][3]);
        *(float4*)(orow + 4) = make_float4(acc[i][4], acc[i][5], acc[i][6], acc[i][7]);
    }
}

// ---------------- per-batch bitonic sort ----------------
__global__ void __launch_bounds__(1024) k_sort() {
    __shared__ float sk[LL];
    __shared__ int   si[LL];
    int b = blockIdx.x, tid = threadIdx.x;
    for (int i = tid; i < LL; i += 1024) { sk[i] = g_ks[b * LL + i]; si[i] = i; }
    __syncthreads();
    for (int k = 2; k <= LL; k <<= 1) {
        for (int j = k >> 1; j > 0; j >>= 1) {
            for (int i = tid; i < LL; i += 1024) {
                int ixj = i ^ j;
                if (ixj > i) {
                    bool asc = ((i & k) == 0);
                    float a = sk[i], c = sk[ixj];
                    bool doswap = asc ? (a > c) : (a < c);
                    if (doswap) {
                        sk[i] = c; sk[ixj] = a;
                        int t = si[i]; si[i] = si[ixj]; si[ixj] = t;
                    }
                }
            }
            __syncthreads();
        }
    }
    for (int i = tid; i < LL; i += 1024) {
        g_ksort[b * LL + i] = sk[i];
        g_ord[b * LL + i]   = si[i];
    }
}

// ---------------- threshold rank per query ----------------
__global__ void k_thresh() {
    int i = blockIdx.x * 256 + threadIdx.x;
    int b = i >> 12;
    float q = g_qs[i];
    const float* ks = g_ksort + b * LL;
    int lo = 0, hi = LL;
    while (lo < hi) {
        int mid = (lo + hi) >> 1;
        if (__ldg(&ks[mid]) < q) lo = mid + 1; else hi = mid;
    }
    g_t[i] = lo;
}

// ---------------- scan phase 1: per-chunk sums (CSZ=32) ----------------
__global__ void __launch_bounds__(256) k_chunksum() {
    int bx = blockIdx.x;
    int b = bx >> 7, c = bx & 127;
    int d = threadIdx.x;
    __shared__ float ev[CSZ];
    __shared__ int   sord[CSZ];
    int base = b * LL + c * CSZ;
    if (d < CSZ) {
        float e = expf(-g_ksort[base + d]);
        ev[d] = e;
        sord[d] = g_ord[base + d];
        // warp-reduce e for chunk E sum
        #pragma unroll
        for (int o = 16; o; o >>= 1) e += __shfl_down_sync(0xffffffffu, e, o);
        if (d == 0) g_chE[b * CH + c] = e;
    }
    __syncthreads();
    float sEV = 0.f, sV = 0.f;
    #pragma unroll 4
    for (int i = 0; i < CSZ; i++) {
        float v = g_V[(size_t)(b * LL + sord[i]) * DD + d];
        sEV = fmaf(ev[i], v, sEV);
        sV += v;
    }
    g_chEV[(b * CH + c) * DD + d] = sEV;
    g_chV [(b * CH + c) * DD + d] = sV;
}

// ---------------- scan phase 2: exclusive scan of chunk sums ----------------
__global__ void __launch_bounds__(256) k_chunkscan() {
    int b = blockIdx.x, d = threadIdx.x;
    float runEV = 0.f, runV = 0.f;
    #pragma unroll 8
    for (int c = 0; c < CH; c++) {
        int idx = (b * CH + c) * DD + d;
        float t1 = g_chEV[idx]; g_chEV[idx] = runEV; runEV += t1;
        float t2 = g_chV[idx];  g_chV[idx]  = runV;  runV  += t2;
    }
    if (d == 0) {
        float run = 0.f;
        #pragma unroll 8
        for (int c = 0; c < CH; c++) {
            float t = g_chE[b * CH + c]; g_chE[b * CH + c] = run; run += t;
        }
    }
}

// ---------------- scan phase 3: emit exclusive prefixes ----------------
__global__ void __launch_bounds__(256) k_emit() {
    int bx = blockIdx.x;
    int b = bx >> 7, c = bx & 127;
    int d = threadIdx.x;
    __shared__ float ev[CSZ];
    __shared__ int   sord[CSZ];
    int base = b * LL + c * CSZ;
    if (d < CSZ) {
        ev[d] = expf(-g_ksort[base + d]);
        sord[d] = g_ord[base + d];
    }
    __syncthreads();
    float aEV = g_chEV[(b * CH + c) * DD + d];
    float aV  = g_chV [(b * CH + c) * DD + d];
    size_t pbase = ((size_t)b * LP1 + c * CSZ) * DD;
    #pragma unroll 4
    for (int i = 0; i < CSZ; i++) {
        g_PEV[pbase + (size_t)i * DD + d] = aEV;
        g_PV [pbase + (size_t)i * DD + d] = aV;
        float v = g_V[(size_t)(b * LL + sord[i]) * DD + d];
        aEV = fmaf(ev[i], v, aEV);
        aV += v;
    }
    if (c == CH - 1) {
        g_PEV[((size_t)b * LP1 + LL) * DD + d] = aEV;
        g_PV [((size_t)b * LP1 + LL) * DD + d] = aV;
    }
    if (d == 0) {
        float aE = g_chE[b * CH + c];
        #pragma unroll
        for (int i = 0; i < CSZ; i++) {
            g_PE[b * LP1 + c * CSZ + i] = aE;
            aE += ev[i];
        }
        if (c == CH - 1) g_PE[b * LP1 + LL] = aE;
    }
}

// ---------------- final output ----------------
__global__ void __launch_bounds__(256) k_out(float* __restrict__ out) {
    int bx = blockIdx.x;
    int b = bx >> 12;
    int d = threadIdx.x;
    int t = g_t[bx];
    float E = expf(g_qs[bx]);
    float den = fmaf(E, g_PE[b * LP1 + t], (float)(LL - t));
    float inv = 1.0f / den;
    size_t pidx = ((size_t)b * LP1 + t)  * DD + d;
    size_t tvix = ((size_t)b * LP1 + LL) * DD + d;
    float suffV = __ldg(&g_PV[tvix]) - g_PV[pidx];
    float num = fmaf(E, g_PEV[pidx], suffV);
    out[(size_t)bx * DD + d] = num * inv;
}

// ---------------- launch ----------------
extern "C" void kernel_launch(void* const* d_in, const int* in_sizes, int n_in,
                              void* d_out, int out_size) {
    const float* x   = (const float*)d_in[0];
    const float* Wq  = (const float*)d_in[1];
    const float* Wk  = (const float*)d_in[2];
    const float* Wv  = (const float*)d_in[3];
    const float* w   = (const float*)d_in[4];
    const float* bm  = (const float*)d_in[5];
    float* out = (float*)d_out;

    k_uvec<<<2, 1024>>>(Wq, Wk, w);
    k_qk<<<BL / 64, 256>>>(x, bm);
    k_vgemm<<<dim3(BL / BM, DD / BN), 256>>>(x, Wv);
    k_sort<<<BB, 1024>>>();
    k_thresh<<<BL / 256, 256>>>();
    k_chunksum<<<BB * CH, 256>>>();
    k_chunkscan<<<BB, 256>>>();
    k_emit<<<BB * CH, 256>>>();
    k_out<<<BL, DD>>>(out);
}

// round 5
// speedup vs baseline: 1.7338x; 1.1787x over previous
#include <cuda_runtime.h>
#include <cstdint>

#define BB 4
#define LL 4096
#define DD 256
#define BL (BB*LL)
#define LP1 (LL+1)
#define CH 128
#define CSZ 32

// ---------------- static scratch ----------------
__device__ float g_V[BL*DD];
__device__ float g_uq[DD];
__device__ float g_uk[DD];
__device__ float g_qs[BL];
__device__ float g_ks[BL];
__device__ float g_ksort[BL];
__device__ int   g_ord[BL];
__device__ int   g_t[BL];
__device__ int   g_rpart[16*BL];
__device__ float g_chE[BB*CH];
__device__ float g_chEV[BB*CH*DD];
__device__ float g_chV[BB*CH*DD];
__device__ float g_PE[BB*LP1];
__device__ float g_PEV[(size_t)BB*LP1*DD];
__device__ float g_PV [(size_t)BB*LP1*DD];

// ---------------- uq = Wq^T w, uk = Wk^T w ----------------
__global__ void __launch_bounds__(1024) k_uvec(const float* __restrict__ Wq,
                                               const float* __restrict__ Wk,
                                               const float* __restrict__ w) {
    __shared__ float part[4][DD];
    const float* W = (blockIdx.x == 0) ? Wq : Wk;
    int d = threadIdx.x & 255, ec = threadIdx.x >> 8;
    float s = 0.f;
    #pragma unroll 8
    for (int e = ec * 64; e < ec * 64 + 64; e++)
        s = fmaf(W[e * DD + d], w[e], s);
    part[ec][d] = s;
    __syncthreads();
    if (ec == 0) {
        float r = part[0][d] + part[1][d] + part[2][d] + part[3][d];
        if (blockIdx.x == 0) g_uq[d] = r; else g_uk[d] = r;
    }
}

// ---------------- per-row scalar q/k ----------------
__global__ void __launch_bounds__(256) k_qk(const float* __restrict__ x,
                                            const float* __restrict__ bptr) {
    __shared__ float suq[DD], suk[DD];
    suq[threadIdx.x] = g_uq[threadIdx.x];
    suk[threadIdx.x] = g_uk[threadIdx.x];
    __syncthreads();
    int warp = threadIdx.x >> 5, lane = threadIdx.x & 31;
    float bias = bptr[0];
    #pragma unroll
    for (int r = 0; r < 8; r++) {
        int m = blockIdx.x * 64 + warp * 8 + r;
        const float* xr = x + (size_t)m * DD;
        float4 xa = *(const float4*)&xr[lane * 4];
        float4 xb = *(const float4*)&xr[128 + lane * 4];
        int da = lane * 4, db = 128 + lane * 4;
        float sq = xa.x * suq[da] + xa.y * suq[da+1] + xa.z * suq[da+2] + xa.w * suq[da+3]
                 + xb.x * suq[db] + xb.y * suq[db+1] + xb.z * suq[db+2] + xb.w * suq[db+3];
        float sk = xa.x * suk[da] + xa.y * suk[da+1] + xa.z * suk[da+2] + xa.w * suk[da+3]
                 + xb.x * suk[db] + xb.y * suk[db+1] + xb.z * suk[db+2] + xb.w * suk[db+3];
        #pragma unroll
        for (int o = 16; o; o >>= 1) {
            sq += __shfl_down_sync(0xffffffffu, sq, o);
            sk += __shfl_down_sync(0xffffffffu, sk, o);
        }
        if (lane == 0) { g_qs[m] = sq + bias; g_ks[m] = sk; }
    }
}

// ---------------- V = x @ Wv^T : 128x128x16 tiles, 8x8 micro (fp32) ----------------
#define BM 128
#define BN 128
#define BK 16
#define APITCH (BM+4)
__global__ void __launch_bounds__(256) k_vgemm(const float* __restrict__ x,
                                               const float* __restrict__ Wv) {
    __shared__ float sA[BK][APITCH];
    __shared__ float sB[BK][APITCH];
    int tid = threadIdx.x;
    int tx = tid & 15, ty = tid >> 4;
    int m0 = blockIdx.x * BM, n0 = blockIdx.y * BN;

    float acc[8][8];
    #pragma unroll
    for (int i = 0; i < 8; i++)
        #pragma unroll
        for (int j = 0; j < 8; j++) acc[i][j] = 0.f;

    for (int k0 = 0; k0 < DD; k0 += BK) {
        #pragma unroll
        for (int p = 0; p < 2; p++) {
            int i = p * 256 + tid;
            int row = i >> 2, kq = i & 3;
            float4 v = *(const float4*)&x[(size_t)(m0 + row) * DD + k0 + kq * 4];
            sA[kq*4+0][row] = v.x; sA[kq*4+1][row] = v.y;
            sA[kq*4+2][row] = v.z; sA[kq*4+3][row] = v.w;
            float4 u = *(const float4*)&Wv[(size_t)(n0 + row) * DD + k0 + kq * 4];
            sB[kq*4+0][row] = u.x; sB[kq*4+1][row] = u.y;
            sB[kq*4+2][row] = u.z; sB[kq*4+3][row] = u.w;
        }
        __syncthreads();
        #pragma unroll
        for (int k = 0; k < BK; k++) {
            float a[8], b[8];
            *(float4*)(a)     = *(float4*)&sA[k][ty * 8];
            *(float4*)(a + 4) = *(float4*)&sA[k][ty * 8 + 4];
            *(float4*)(b)     = *(float4*)&sB[k][tx * 8];
            *(float4*)(b + 4) = *(float4*)&sB[k][tx * 8 + 4];
            #pragma unroll
            for (int i = 0; i < 8; i++)
                #pragma unroll
                for (int j = 0; j < 8; j++)
                    acc[i][j] = fmaf(a[i], b[j], acc[i][j]);
        }
        __syncthreads();
    }
    #pragma unroll
    for (int i = 0; i < 8; i++) {
        float* orow = &g_V[(size_t)(m0 + ty * 8 + i) * DD + n0 + tx * 8];
        *(float4*)(orow)     = make_float4(acc[i][0], acc[i][1], acc[i][2], acc[i][3]);
        *(float4*)(orow + 4) = make_float4(acc[i][4], acc[i][5], acc[i][6], acc[i][7]);
    }
}

// ---------------- rank by counting (exact, tie-broken by index) ----------------
__global__ void __launch_bounds__(256) k_rank() {
    __shared__ uint32_t ik[256];
    int jb = blockIdx.x;          // 0..7 (2048 j's each)
    int ic = blockIdx.y;          // 0..15 (256 i's each, within jb's batch)
    int batch = jb >> 1;
    int ibase = batch * LL + ic * 256;
    {
        uint32_t u = __float_as_uint(g_ks[ibase + threadIdx.x]);
        ik[threadIdx.x] = ((int)u < 0) ? ~u : (u | 0x80000000u);
    }
    int j0 = jb * 2048 + threadIdx.x * 8;
    int jloc0 = j0 & (LL - 1);
    uint32_t uj[8]; int cnt[8];
    #pragma unroll
    for (int r = 0; r < 8; r++) {
        uint32_t u = __float_as_uint(g_ks[j0 + r]);
        uj[r] = ((int)u < 0) ? ~u : (u | 0x80000000u);
        cnt[r] = 0;
    }
    __syncthreads();
    int gib = ic * 256;
    #pragma unroll 4
    for (int ii = 0; ii < 256; ii++) {
        uint32_t ui = ik[ii];
        int gi = gib + ii;
        #pragma unroll
        for (int r = 0; r < 8; r++)
            cnt[r] += (int)((ui < uj[r]) | ((ui == uj[r]) & (gi < jloc0 + r)));
    }
    #pragma unroll
    for (int r = 0; r < 8; r++) g_rpart[ic * BL + j0 + r] = cnt[r];
}

__global__ void k_ranksum() {
    int j = blockIdx.x * 256 + threadIdx.x;
    int sum = 0;
    #pragma unroll
    for (int ic = 0; ic < 16; ic++) sum += g_rpart[ic * BL + j];
    int b = j >> 12;
    g_ksort[b * LL + sum] = g_ks[j];
    g_ord[b * LL + sum]   = j & (LL - 1);
}

// ---------------- threshold rank per query ----------------
__global__ void k_thresh() {
    int i = blockIdx.x * 256 + threadIdx.x;
    int b = i >> 12;
    float q = g_qs[i];
    const float* ks = g_ksort + b * LL;
    int lo = 0, hi = LL;
    while (lo < hi) {
        int mid = (lo + hi) >> 1;
        if (__ldg(&ks[mid]) < q) lo = mid + 1; else hi = mid;
    }
    g_t[i] = lo;
}

// ---------------- scan phase 1 ----------------
__global__ void __launch_bounds__(256) k_chunksum() {
    int bx = blockIdx.x;
    int b = bx >> 7, c = bx & 127;
    int d = threadIdx.x;
    __shared__ float ev[CSZ];
    __shared__ int   sord[CSZ];
    int base = b * LL + c * CSZ;
    if (d < CSZ) {
        float e = expf(-g_ksort[base + d]);
        ev[d] = e;
        sord[d] = g_ord[base + d];
        #pragma unroll
        for (int o = 16; o; o >>= 1) e += __shfl_down_sync(0xffffffffu, e, o);
        if (d == 0) g_chE[b * CH + c] = e;
    }
    __syncthreads();
    float sEV = 0.f, sV = 0.f;
    #pragma unroll 4
    for (int i = 0; i < CSZ; i++) {
        float v = g_V[(size_t)(b * LL + sord[i]) * DD + d];
        sEV = fmaf(ev[i], v, sEV);
        sV += v;
    }
    g_chEV[(b * CH + c) * DD + d] = sEV;
    g_chV [(b * CH + c) * DD + d] = sV;
}

// ---------------- scan phase 2 ----------------
__global__ void __launch_bounds__(256) k_chunkscan() {
    int b = blockIdx.x, d = threadIdx.x;
    float runEV = 0.f, runV = 0.f;
    #pragma unroll 8
    for (int c = 0; c < CH; c++) {
        int idx = (b * CH + c) * DD + d;
        float t1 = g_chEV[idx]; g_chEV[idx] = runEV; runEV += t1;
        float t2 = g_chV[idx];  g_chV[idx]  = runV;  runV  += t2;
    }
    if (d == 0) {
        float run = 0.f;
        #pragma unroll 8
        for (int c = 0; c < CH; c++) {
            float t = g_chE[b * CH + c]; g_chE[b * CH + c] = run; run += t;
        }
    }
}

// ---------------- scan phase 3 ----------------
__global__ void __launch_bounds__(256) k_emit() {
    int bx = blockIdx.x;
    int b = bx >> 7, c = bx & 127;
    int d = threadIdx.x;
    __shared__ float ev[CSZ];
    __shared__ int   sord[CSZ];
    int base = b * LL + c * CSZ;
    if (d < CSZ) {
        ev[d] = expf(-g_ksort[base + d]);
        sord[d] = g_ord[base + d];
    }
    __syncthreads();
    float aEV = g_chEV[(b * CH + c) * DD + d];
    float aV  = g_chV [(b * CH + c) * DD + d];
    size_t pbase = ((size_t)b * LP1 + c * CSZ) * DD;
    #pragma unroll 4
    for (int i = 0; i < CSZ; i++) {
        g_PEV[pbase + (size_t)i * DD + d] = aEV;
        g_PV [pbase + (size_t)i * DD + d] = aV;
        float v = g_V[(size_t)(b * LL + sord[i]) * DD + d];
        aEV = fmaf(ev[i], v, aEV);
        aV += v;
    }
    if (c == CH - 1) {
        g_PEV[((size_t)b * LP1 + LL) * DD + d] = aEV;
        g_PV [((size_t)b * LP1 + LL) * DD + d] = aV;
    }
    if (d == 0) {
        float aE = g_chE[b * CH + c];
        #pragma unroll
        for (int i = 0; i < CSZ; i++) {
            g_PE[b * LP1 + c * CSZ + i] = aE;
            aE += ev[i];
        }
        if (c == CH - 1) g_PE[b * LP1 + LL] = aE;
    }
}

// ---------------- final output ----------------
__global__ void __launch_bounds__(256) k_out(float* __restrict__ out) {
    int bx = blockIdx.x;
    int b = bx >> 12;
    int d = threadIdx.x;
    int t = g_t[bx];
    float E = expf(g_qs[bx]);
    float den = fmaf(E, g_PE[b * LP1 + t], (float)(LL - t));
    float inv = 1.0f / den;
    size_t pidx = ((size_t)b * LP1 + t)  * DD + d;
    size_t tvix = ((size_t)b * LP1 + LL) * DD + d;
    float suffV = __ldg(&g_PV[tvix]) - g_PV[pidx];
    float num = fmaf(E, g_PEV[pidx], suffV);
    out[(size_t)bx * DD + d] = num * inv;
}

// ---------------- launch ----------------
extern "C" void kernel_launch(void* const* d_in, const int* in_sizes, int n_in,
                              void* d_out, int out_size) {
    const float* x   = (const float*)d_in[0];
    const float* Wq  = (const float*)d_in[1];
    const float* Wk  = (const float*)d_in[2];
    const float* Wv  = (const float*)d_in[3];
    const float* w   = (const float*)d_in[4];
    const float* bm  = (const float*)d_in[5];
    float* out = (float*)d_out;

    k_uvec<<<2, 1024>>>(Wq, Wk, w);
    k_qk<<<BL / 64, 256>>>(x, bm);
    k_vgemm<<<dim3(BL / BM, DD / BN), 256>>>(x, Wv);
    k_rank<<<dim3(8, 16), 256>>>();
    k_ranksum<<<BL / 256, 256>>>();
    k_thresh<<<BL / 256, 256>>>();
    k_chunksum<<<BB * CH, 256>>>();
    k_chunkscan<<<BB, 256>>>();
    k_emit<<<BB * CH, 256>>>();
    k_out<<<BL, DD>>>(out);
}

// round 6
// speedup vs baseline: 2.2146x; 1.2773x over previous
#include <cuda_runtime.h>
#include <cuda_bf16.h>
#include <cstdint>

#define BB 4
#define LL 4096
#define DD 256
#define BL (BB*LL)
#define LP1 (LL+1)
#define CH 128
#define CSZ 32

// ---------------- static scratch ----------------
__device__ float g_V[BL*DD];
__device__ float g_uq[DD];
__device__ float g_uk[DD];
__device__ float g_qs[BL];
__device__ float g_ks[BL];
__device__ float g_ksort[BL];
__device__ int   g_ord[BL];
__device__ int   g_t[BL];
__device__ int   g_rpart[32*BL];
__device__ float g_chE[BB*CH];
__device__ float g_chEV[BB*CH*DD];
__device__ float g_chV[BB*CH*DD];
__device__ float g_PE[BB*LP1];
__device__ float g_PEV[(size_t)BB*LP1*DD];
__device__ float g_PV [(size_t)BB*LP1*DD];

// ---------------- uq = Wq^T w, uk = Wk^T w ----------------
__global__ void __launch_bounds__(1024) k_uvec(const float* __restrict__ Wq,
                                               const float* __restrict__ Wk,
                                               const float* __restrict__ w) {
    __shared__ float part[4][DD];
    const float* W = (blockIdx.x == 0) ? Wq : Wk;
    int d = threadIdx.x & 255, ec = threadIdx.x >> 8;
    float s = 0.f;
    #pragma unroll 8
    for (int e = ec * 64; e < ec * 64 + 64; e++)
        s = fmaf(W[e * DD + d], w[e], s);
    part[ec][d] = s;
    __syncthreads();
    if (ec == 0) {
        float r = part[0][d] + part[1][d] + part[2][d] + part[3][d];
        if (blockIdx.x == 0) g_uq[d] = r; else g_uk[d] = r;
    }
}

// ---------------- per-row scalar q/k ----------------
__global__ void __launch_bounds__(256) k_qk(const float* __restrict__ x,
                                            const float* __restrict__ bptr) {
    __shared__ float suq[DD], suk[DD];
    suq[threadIdx.x] = g_uq[threadIdx.x];
    suk[threadIdx.x] = g_uk[threadIdx.x];
    __syncthreads();
    int warp = threadIdx.x >> 5, lane = threadIdx.x & 31;
    float bias = bptr[0];
    #pragma unroll
    for (int r = 0; r < 8; r++) {
        int m = blockIdx.x * 64 + warp * 8 + r;
        const float* xr = x + (size_t)m * DD;
        float4 xa = *(const float4*)&xr[lane * 4];
        float4 xb = *(const float4*)&xr[128 + lane * 4];
        int da = lane * 4, db = 128 + lane * 4;
        float sq = xa.x * suq[da] + xa.y * suq[da+1] + xa.z * suq[da+2] + xa.w * suq[da+3]
                 + xb.x * suq[db] + xb.y * suq[db+1] + xb.z * suq[db+2] + xb.w * suq[db+3];
        float sk = xa.x * suk[da] + xa.y * suk[da+1] + xa.z * suk[da+2] + xa.w * suk[da+3]
                 + xb.x * suk[db] + xb.y * suk[db+1] + xb.z * suk[db+2] + xb.w * suk[db+3];
        #pragma unroll
        for (int o = 16; o; o >>= 1) {
            sq += __shfl_down_sync(0xffffffffu, sq, o);
            sk += __shfl_down_sync(0xffffffffu, sk, o);
        }
        if (lane == 0) { g_qs[m] = sq + bias; g_ks[m] = sk; }
    }
}

// ---------------- V = x @ Wv^T : mma.sync bf16 3-pass split ----------------
#define PITCH 36
__device__ __forceinline__ void mma_bf16(float* d, const uint32_t* a, const uint32_t* b) {
    asm volatile("mma.sync.aligned.m16n8k16.row.col.f32.bf16.bf16.f32 "
        "{%0,%1,%2,%3}, {%4,%5,%6,%7}, {%8,%9}, {%0,%1,%2,%3};"
        : "+f"(d[0]), "+f"(d[1]), "+f"(d[2]), "+f"(d[3])
        : "r"(a[0]), "r"(a[1]), "r"(a[2]), "r"(a[3]), "r"(b[0]), "r"(b[1]));
}

__global__ void __launch_bounds__(256) k_vgemm(const float* __restrict__ x,
                                               const float* __restrict__ Wv) {
    __shared__ __nv_bfloat16 sAh[128][PITCH], sAl[128][PITCH];
    __shared__ __nv_bfloat16 sBh[128][PITCH], sBl[128][PITCH];
    int tid = threadIdx.x, wid = tid >> 5, lane = tid & 31;
    int g = lane >> 2, t4 = lane & 3;
    int wr = wid >> 2, wc = wid & 3;
    int m0 = blockIdx.x * 128, n0 = blockIdx.y * 128;

    float acc[4][4][4];
    #pragma unroll
    for (int mt = 0; mt < 4; mt++)
        #pragma unroll
        for (int nt = 0; nt < 4; nt++)
            #pragma unroll
            for (int e = 0; e < 4; e++) acc[mt][nt][e] = 0.f;

    for (int k0 = 0; k0 < DD; k0 += 32) {
        #pragma unroll
        for (int p = 0; p < 8; p++) {
            int s = p * 256 + tid;             // 0..2047
            int row = (s & 1023) >> 3, kq = s & 7;
            const float* src = (s < 1024)
                ? &x [(size_t)(m0 + row) * DD + k0 + kq * 4]
                : &Wv[(size_t)(n0 + row) * DD + k0 + kq * 4];
            float4 v = *(const float4*)src;
            __nv_bfloat162 h0 = __floats2bfloat162_rn(v.x, v.y);
            __nv_bfloat162 h1 = __floats2bfloat162_rn(v.z, v.w);
            __nv_bfloat162 l0 = __floats2bfloat162_rn(v.x - __low2float(h0),
                                                      v.y - __high2float(h0));
            __nv_bfloat162 l1 = __floats2bfloat162_rn(v.z - __low2float(h1),
                                                      v.w - __high2float(h1));
            __nv_bfloat16* dh = (s < 1024) ? &sAh[row][kq * 4] : &sBh[row][kq * 4];
            __nv_bfloat16* dl = (s < 1024) ? &sAl[row][kq * 4] : &sBl[row][kq * 4];
            *(uint2*)dh = make_uint2(*(uint32_t*)&h0, *(uint32_t*)&h1);
            *(uint2*)dl = make_uint2(*(uint32_t*)&l0, *(uint32_t*)&l1);
        }
        __syncthreads();
        #pragma unroll
        for (int ks = 0; ks < 32; ks += 16) {
            uint32_t ah[4][4], al[4][4], bh[4][2], bl[4][2];
            #pragma unroll
            for (int mt = 0; mt < 4; mt++) {
                int rb = wr * 64 + mt * 16;
                int kc = ks + 2 * t4;
                ah[mt][0] = *(uint32_t*)&sAh[rb + g    ][kc];
                ah[mt][1] = *(uint32_t*)&sAh[rb + g + 8][kc];
                ah[mt][2] = *(uint32_t*)&sAh[rb + g    ][kc + 8];
                ah[mt][3] = *(uint32_t*)&sAh[rb + g + 8][kc + 8];
                al[mt][0] = *(uint32_t*)&sAl[rb + g    ][kc];
                al[mt][1] = *(uint32_t*)&sAl[rb + g + 8][kc];
                al[mt][2] = *(uint32_t*)&sAl[rb + g    ][kc + 8];
                al[mt][3] = *(uint32_t*)&sAl[rb + g + 8][kc + 8];
            }
            #pragma unroll
            for (int nt = 0; nt < 4; nt++) {
                int nb = wc * 32 + nt * 8;
                int kc = ks + 2 * t4;
                bh[nt][0] = *(uint32_t*)&sBh[nb + g][kc];
                bh[nt][1] = *(uint32_t*)&sBh[nb + g][kc + 8];
                bl[nt][0] = *(uint32_t*)&sBl[nb + g][kc];
                bl[nt][1] = *(uint32_t*)&sBl[nb + g][kc + 8];
            }
            #pragma unroll
            for (int mt = 0; mt < 4; mt++)
                #pragma unroll
                for (int nt = 0; nt < 4; nt++) {
                    mma_bf16(acc[mt][nt], ah[mt], bh[nt]);
                    mma_bf16(acc[mt][nt], ah[mt], bl[nt]);
                    mma_bf16(acc[mt][nt], al[mt], bh[nt]);
                }
        }
        __syncthreads();
    }
    #pragma unroll
    for (int mt = 0; mt < 4; mt++)
        #pragma unroll
        for (int nt = 0; nt < 4; nt++) {
            int m = m0 + wr * 64 + mt * 16 + g;
            int n = n0 + wc * 32 + nt * 8 + 2 * t4;
            *(float2*)&g_V[(size_t)m * DD + n] =
                make_float2(acc[mt][nt][0], acc[mt][nt][1]);
            *(float2*)&g_V[(size_t)(m + 8) * DD + n] =
                make_float2(acc[mt][nt][2], acc[mt][nt][3]);
        }
}

// ---------------- rank by counting (exact, tie-broken by index) ----------------
__global__ void __launch_bounds__(256) k_rank() {
    __shared__ uint32_t ik[128];
    int jb = blockIdx.x;          // 0..15 (1024 j's each)
    int ic = blockIdx.y;          // 0..31 (128 i's each)
    int batch = jb >> 2;
    int ibase = batch * LL + ic * 128;
    if (threadIdx.x < 128) {
        uint32_t u = __float_as_uint(g_ks[ibase + threadIdx.x]);
        ik[threadIdx.x] = ((int)u < 0) ? ~u : (u | 0x80000000u);
    }
    int j0 = jb * 1024 + threadIdx.x * 4;
    int jloc0 = j0 & (LL - 1);
    uint32_t uj[4]; int cnt[4];
    #pragma unroll
    for (int r = 0; r < 4; r++) {
        uint32_t u = __float_as_uint(g_ks[j0 + r]);
        uj[r] = ((int)u < 0) ? ~u : (u | 0x80000000u);
        cnt[r] = 0;
    }
    __syncthreads();
    int gib = ic * 128;
    #pragma unroll 4
    for (int ii = 0; ii < 128; ii++) {
        uint32_t ui = ik[ii];
        int gi = gib + ii;
        #pragma unroll
        for (int r = 0; r < 4; r++)
            cnt[r] += (int)((ui < uj[r]) | ((ui == uj[r]) & (gi < jloc0 + r)));
    }
    #pragma unroll
    for (int r = 0; r < 4; r++) g_rpart[ic * BL + j0 + r] = cnt[r];
}

__global__ void k_ranksum() {
    int j = blockIdx.x * 256 + threadIdx.x;
    int sum = 0;
    #pragma unroll
    for (int ic = 0; ic < 32; ic++) sum += g_rpart[ic * BL + j];
    int b = j >> 12;
    g_ksort[b * LL + sum] = g_ks[j];
    g_ord[b * LL + sum]   = j & (LL - 1);
}

// ---------------- threshold rank per query ----------------
__global__ void k_thresh() {
    int i = blockIdx.x * 256 + threadIdx.x;
    int b = i >> 12;
    float q = g_qs[i];
    const float* ks = g_ksort + b * LL;
    int lo = 0, hi = LL;
    while (lo < hi) {
        int mid = (lo + hi) >> 1;
        if (__ldg(&ks[mid]) < q) lo = mid + 1; else hi = mid;
    }
    g_t[i] = lo;
}

// ---------------- scan phase 1 ----------------
__global__ void __launch_bounds__(256) k_chunksum() {
    int bx = blockIdx.x;
    int b = bx >> 7, c = bx & 127;
    int d = threadIdx.x;
    __shared__ float ev[CSZ];
    __shared__ int   sord[CSZ];
    int base = b * LL + c * CSZ;
    if (d < CSZ) {
        float e = expf(-g_ksort[base + d]);
        ev[d] = e;
        sord[d] = g_ord[base + d];
        #pragma unroll
        for (int o = 16; o; o >>= 1) e += __shfl_down_sync(0xffffffffu, e, o);
        if (d == 0) g_chE[b * CH + c] = e;
    }
    __syncthreads();
    float sEV = 0.f, sV = 0.f;
    #pragma unroll 4
    for (int i = 0; i < CSZ; i++) {
        float v = g_V[(size_t)(b * LL + sord[i]) * DD + d];
        sEV = fmaf(ev[i], v, sEV);
        sV += v;
    }
    g_chEV[(b * CH + c) * DD + d] = sEV;
    g_chV [(b * CH + c) * DD + d] = sV;
}

// ---------------- scan phase 2 ----------------
__global__ void __launch_bounds__(256) k_chunkscan() {
    int b = blockIdx.x, d = threadIdx.x;
    float runEV = 0.f, runV = 0.f;
    #pragma unroll 8
    for (int c = 0; c < CH; c++) {
        int idx = (b * CH + c) * DD + d;
        float t1 = g_chEV[idx]; g_chEV[idx] = runEV; runEV += t1;
        float t2 = g_chV[idx];  g_chV[idx]  = runV;  runV  += t2;
    }
    if (d == 0) {
        float run = 0.f;
        #pragma unroll 8
        for (int c = 0; c < CH; c++) {
            float t = g_chE[b * CH + c]; g_chE[b * CH + c] = run; run += t;
        }
    }
}

// ---------------- scan phase 3 ----------------
__global__ void __launch_bounds__(256) k_emit() {
    int bx = blockIdx.x;
    int b = bx >> 7, c = bx & 127;
    int d = threadIdx.x;
    __shared__ float ev[CSZ];
    __shared__ int   sord[CSZ];
    int base = b * LL + c * CSZ;
    if (d < CSZ) {
        ev[d] = expf(-g_ksort[base + d]);
        sord[d] = g_ord[base + d];
    }
    __syncthreads();
    float aEV = g_chEV[(b * CH + c) * DD + d];
    float aV  = g_chV [(b * CH + c) * DD + d];
    size_t pbase = ((size_t)b * LP1 + c * CSZ) * DD;
    #pragma unroll 4
    for (int i = 0; i < CSZ; i++) {
        g_PEV[pbase + (size_t)i * DD + d] = aEV;
        g_PV [pbase + (size_t)i * DD + d] = aV;
        float v = g_V[(size_t)(b * LL + sord[i]) * DD + d];
        aEV = fmaf(ev[i], v, aEV);
        aV += v;
    }
    if (c == CH - 1) {
        g_PEV[((size_t)b * LP1 + LL) * DD + d] = aEV;
        g_PV [((size_t)b * LP1 + LL) * DD + d] = aV;
    }
    if (d == 0) {
        float aE = g_chE[b * CH + c];
        #pragma unroll
        for (int i = 0; i < CSZ; i++) {
            g_PE[b * LP1 + c * CSZ + i] = aE;
            aE += ev[i];
        }
        if (c == CH - 1) g_PE[b * LP1 + LL] = aE;
    }
}

// ---------------- final output ----------------
__global__ void __launch_bounds__(256) k_out(float* __restrict__ out) {
    int bx = blockIdx.x;
    int b = bx >> 12;
    int d = threadIdx.x;
    int t = g_t[bx];
    float E = expf(g_qs[bx]);
    float den = fmaf(E, g_PE[b * LP1 + t], (float)(LL - t));
    float inv = 1.0f / den;
    size_t pidx = ((size_t)b * LP1 + t)  * DD + d;
    size_t tvix = ((size_t)b * LP1 + LL) * DD + d;
    float suffV = __ldg(&g_PV[tvix]) - g_PV[pidx];
    float num = fmaf(E, g_PEV[pidx], suffV);
    out[(size_t)bx * DD + d] = num * inv;
}

// ---------------- launch ----------------
extern "C" void kernel_launch(void* const* d_in, const int* in_sizes, int n_in,
                              void* d_out, int out_size) {
    const float* x   = (const float*)d_in[0];
    const float* Wq  = (const float*)d_in[1];
    const float* Wk  = (const float*)d_in[2];
    const float* Wv  = (const float*)d_in[3];
    const float* w   = (const float*)d_in[4];
    const float* bm  = (const float*)d_in[5];
    float* out = (float*)d_out;

    k_uvec<<<2, 1024>>>(Wq, Wk, w);
    k_qk<<<BL / 64, 256>>>(x, bm);
    k_vgemm<<<dim3(BL / 128, DD / 128), 256>>>(x, Wv);
    k_rank<<<dim3(16, 32), 256>>>();
    k_ranksum<<<BL / 256, 256>>>();
    k_thresh<<<BL / 256, 256>>>();
    k_chunksum<<<BB * CH, 256>>>();
    k_chunkscan<<<BB, 256>>>();
    k_emit<<<BB * CH, 256>>>();
    k_out<<<BL, DD>>>(out);
}

// round 9
// speedup vs baseline: 2.2754x; 1.0274x over previous
#include <cuda_runtime.h>
#include <cuda_bf16.h>
#include <cstdint>

#define BB 4
#define LL 4096
#define DD 256
#define BL (BB*LL)
#define NB 129          // chunk bins per batch (128 chunks + overflow t=4096)
#define NBT (BB*NB)     // 516 total bins

// ---------------- static scratch ----------------
__device__ float g_V[BL*DD];
__device__ float g_uq[DD];
__device__ float g_uk[DD];
__device__ float g_qs[BL];
__device__ float g_ks[BL];
__device__ float g_ksort[BL];
__device__ int   g_ord[BL];
__device__ int   g_t[BL];
__device__ unsigned long long g_tk[BL];   // per-tile sorted packed keys
__device__ int   g_rpart[16*BL];
__device__ float g_chE[BB*NB];
__device__ float g_chEV[BB*NB*DD];
__device__ float g_chV[BB*NB*DD];
__device__ int   g_bincnt[NBT];
__device__ int   g_bincur[NBT];
__device__ int   g_binoff[NBT+1];
__device__ int   g_qlist[BL];

__device__ __forceinline__ uint32_t fmap(float f) {
    uint32_t u = __float_as_uint(f);
    return ((int)u < 0) ? ~u : (u | 0x80000000u);
}

// ---------------- uq = Wq^T w, uk = Wk^T w ----------------
__global__ void __launch_bounds__(1024) k_uvec(const float* __restrict__ Wq,
                                               const float* __restrict__ Wk,
                                               const float* __restrict__ w) {
    __shared__ float part[4][DD];
    const float* W = (blockIdx.x == 0) ? Wq : Wk;
    int d = threadIdx.x & 255, ec = threadIdx.x >> 8;
    float s = 0.f;
    #pragma unroll 8
    for (int e = ec * 64; e < ec * 64 + 64; e++)
        s = fmaf(W[e * DD + d], w[e], s);
    part[ec][d] = s;
    __syncthreads();
    if (ec == 0) {
        float r = part[0][d] + part[1][d] + part[2][d] + part[3][d];
        if (blockIdx.x == 0) g_uq[d] = r; else g_uk[d] = r;
    }
}

// ---------------- per-row scalar q/k ----------------
__global__ void __launch_bounds__(256) k_qk(const float* __restrict__ x,
                                            const float* __restrict__ bptr) {
    __shared__ float suq[DD], suk[DD];
    suq[threadIdx.x] = g_uq[threadIdx.x];
    suk[threadIdx.x] = g_uk[threadIdx.x];
    __syncthreads();
    int warp = threadIdx.x >> 5, lane = threadIdx.x & 31;
    float bias = bptr[0];
    #pragma unroll
    for (int r = 0; r < 8; r++) {
        int m = blockIdx.x * 64 + warp * 8 + r;
        const float* xr = x + (size_t)m * DD;
        float4 xa = *(const float4*)&xr[lane * 4];
        float4 xb = *(const float4*)&xr[128 + lane * 4];
        int da = lane * 4, db = 128 + lane * 4;
        float sq = xa.x * suq[da] + xa.y * suq[da+1] + xa.z * suq[da+2] + xa.w * suq[da+3]
                 + xb.x * suq[db] + xb.y * suq[db+1] + xb.z * suq[db+2] + xb.w * suq[db+3];
        float sk = xa.x * suk[da] + xa.y * suk[da+1] + xa.z * suk[da+2] + xa.w * suk[da+3]
                 + xb.x * suk[db] + xb.y * suk[db+1] + xb.z * suk[db+2] + xb.w * suk[db+3];
        #pragma unroll
        for (int o = 16; o; o >>= 1) {
            sq += __shfl_down_sync(0xffffffffu, sq, o);
            sk += __shfl_down_sync(0xffffffffu, sk, o);
        }
        if (lane == 0) { g_qs[m] = sq + bias; g_ks[m] = sk; }
    }
}

// ---------------- V = x @ Wv^T : mma.sync bf16 3-pass split ----------------
#define PITCH 36
__device__ __forceinline__ void mma_bf16(float* d, const uint32_t* a, const uint32_t* b) {
    asm volatile("mma.sync.aligned.m16n8k16.row.col.f32.bf16.bf16.f32 "
        "{%0,%1,%2,%3}, {%4,%5,%6,%7}, {%8,%9}, {%0,%1,%2,%3};"
        : "+f"(d[0]), "+f"(d[1]), "+f"(d[2]), "+f"(d[3])
        : "r"(a[0]), "r"(a[1]), "r"(a[2]), "r"(a[3]), "r"(b[0]), "r"(b[1]));
}

__global__ void __launch_bounds__(256) k_vgemm(const float* __restrict__ x,
                                               const float* __restrict__ Wv) {
    __shared__ __nv_bfloat16 sAh[128][PITCH], sAl[128][PITCH];
    __shared__ __nv_bfloat16 sBh[128][PITCH], sBl[128][PITCH];
    int tid = threadIdx.x, wid = tid >> 5, lane = tid & 31;
    int g = lane >> 2, t4 = lane & 3;
    int wr = wid >> 2, wc = wid & 3;
    int m0 = blockIdx.x * 128, n0 = blockIdx.y * 128;

    float acc[4][4][4];
    #pragma unroll
    for (int mt = 0; mt < 4; mt++)
        #pragma unroll
        for (int nt = 0; nt < 4; nt++)
            #pragma unroll
            for (int e = 0; e < 4; e++) acc[mt][nt][e] = 0.f;

    for (int k0 = 0; k0 < DD; k0 += 32) {
        #pragma unroll
        for (int p = 0; p < 8; p++) {
            int s = p * 256 + tid;
            int row = (s & 1023) >> 3, kq = s & 7;
            const float* src = (s < 1024)
                ? &x [(size_t)(m0 + row) * DD + k0 + kq * 4]
                : &Wv[(size_t)(n0 + row) * DD + k0 + kq * 4];
            float4 v = *(const float4*)src;
            __nv_bfloat162 h0 = __floats2bfloat162_rn(v.x, v.y);
            __nv_bfloat162 h1 = __floats2bfloat162_rn(v.z, v.w);
            __nv_bfloat162 l0 = __floats2bfloat162_rn(v.x - __low2float(h0),
                                                      v.y - __high2float(h0));
            __nv_bfloat162 l1 = __floats2bfloat162_rn(v.z - __low2float(h1),
                                                      v.w - __high2float(h1));
            __nv_bfloat16* dh = (s < 1024) ? &sAh[row][kq * 4] : &sBh[row][kq * 4];
            __nv_bfloat16* dl = (s < 1024) ? &sAl[row][kq * 4] : &sBl[row][kq * 4];
            *(uint2*)dh = make_uint2(*(uint32_t*)&h0, *(uint32_t*)&h1);
            *(uint2*)dl = make_uint2(*(uint32_t*)&l0, *(uint32_t*)&l1);
        }
        __syncthreads();
        #pragma unroll
        for (int ks = 0; ks < 32; ks += 16) {
            uint32_t ah[4][4], al[4][4], bh[4][2], bl[4][2];
            #pragma unroll
            for (int mt = 0; mt < 4; mt++) {
                int rb = wr * 64 + mt * 16;
                int kc = ks + 2 * t4;
                ah[mt][0] = *(uint32_t*)&sAh[rb + g    ][kc];
                ah[mt][1] = *(uint32_t*)&sAh[rb + g + 8][kc];
                ah[mt][2] = *(uint32_t*)&sAh[rb + g    ][kc + 8];
                ah[mt][3] = *(uint32_t*)&sAh[rb + g + 8][kc + 8];
                al[mt][0] = *(uint32_t*)&sAl[rb + g    ][kc];
                al[mt][1] = *(uint32_t*)&sAl[rb + g + 8][kc];
                al[mt][2] = *(uint32_t*)&sAl[rb + g    ][kc + 8];
                al[mt][3] = *(uint32_t*)&sAl[rb + g + 8][kc + 8];
            }
            #pragma unroll
            for (int nt = 0; nt < 4; nt++) {
                int nb = wc * 32 + nt * 8;
                int kc = ks + 2 * t4;
                bh[nt][0] = *(uint32_t*)&sBh[nb + g][kc];
                bh[nt][1] = *(uint32_t*)&sBh[nb + g][kc + 8];
                bl[nt][0] = *(uint32_t*)&sBl[nb + g][kc];
                bl[nt][1] = *(uint32_t*)&sBl[nb + g][kc + 8];
            }
            #pragma unroll
            for (int mt = 0; mt < 4; mt++)
                #pragma unroll
                for (int nt = 0; nt < 4; nt++) {
                    mma_bf16(acc[mt][nt], ah[mt], bh[nt]);
                    mma_bf16(acc[mt][nt], ah[mt], bl[nt]);
                    mma_bf16(acc[mt][nt], al[mt], bh[nt]);
                }
        }
        __syncthreads();
    }
    #pragma unroll
    for (int mt = 0; mt < 4; mt++)
        #pragma unroll
        for (int nt = 0; nt < 4; nt++) {
            int m = m0 + wr * 64 + mt * 16 + g;
            int n = n0 + wc * 32 + nt * 8 + 2 * t4;
            *(float2*)&g_V[(size_t)m * DD + n] =
                make_float2(acc[mt][nt][0], acc[mt][nt][1]);
            *(float2*)&g_V[(size_t)(m + 8) * DD + n] =
                make_float2(acc[mt][nt][2], acc[mt][nt][3]);
        }
}

// ---------------- sort 256-key tiles (bitonic, u64 packed keys) ----------------
__global__ void __launch_bounds__(256) k_tsort() {
    __shared__ unsigned long long sk[256];
    int base = blockIdx.x * 256;
    int tid = threadIdx.x;
    int jloc = (base + tid) & (LL - 1);
    sk[tid] = ((unsigned long long)fmap(g_ks[base + tid]) << 12) | (unsigned)jloc;
    __syncthreads();
    for (int k = 2; k <= 256; k <<= 1) {
        for (int j = k >> 1; j > 0; j >>= 1) {
            int ixj = tid ^ j;
            if (ixj > tid) {
                bool asc = ((tid & k) == 0);
                unsigned long long a = sk[tid], c = sk[ixj];
                if (asc ? (a > c) : (a < c)) { sk[tid] = c; sk[ixj] = a; }
            }
            __syncthreads();
        }
    }
    g_tk[base + tid] = sk[tid];
}

// ---------------- rank = sum of lower_bounds over 16 sorted tiles ----------------
__global__ void __launch_bounds__(256) k_rank2() {
    __shared__ unsigned long long st[256];
    int tile = blockIdx.x;            // 0..63
    int batch = tile >> 4;
    int tid = threadIdx.x;
    st[tid] = g_tk[tile * 256 + tid];
    int j = batch * LL + blockIdx.y * 256 + tid;
    unsigned long long kj = ((unsigned long long)fmap(g_ks[j]) << 12)
                          | (unsigned)(j & (LL - 1));
    __syncthreads();
    // exact lower_bound (count of elements < kj), range [0,256]
    int pos;
    if (st[255] < kj) {
        pos = 256;                     // kj exceeds all tile elements
    } else {
        pos = 0;                       // count <= 255: 8-step bisection exact
        #pragma unroll
        for (int step = 128; step; step >>= 1)
            if (st[pos + step - 1] < kj) pos += step;
    }
    g_rpart[(tile & 15) * BL + j] = pos;
}

__global__ void k_ranksum() {
    int j = blockIdx.x * 256 + threadIdx.x;
    int sum = 0;
    #pragma unroll
    for (int ic = 0; ic < 16; ic++) sum += g_rpart[ic * BL + j];
    int b = j >> 12;
    g_ksort[b * LL + sum] = g_ks[j];
    g_ord[b * LL + sum]   = j & (LL - 1);
}

// ---------------- zero bin counters ----------------
__global__ void k_zero() {
    int i = threadIdx.x + blockIdx.x * 1024;
    if (i < NBT) { g_bincnt[i] = 0; g_bincur[i] = 0; }
}

// ---------------- threshold rank + histogram ----------------
__global__ void k_thresh_hist() {
    int i = blockIdx.x * 256 + threadIdx.x;
    int b = i >> 12;
    float q = g_qs[i];
    const float* ks = g_ksort + b * LL;
    int lo = 0, hi = LL;
    while (lo < hi) {
        int mid = (lo + hi) >> 1;
        if (__ldg(&ks[mid]) < q) lo = mid + 1; else hi = mid;
    }
    g_t[i] = lo;
    atomicAdd(&g_bincnt[b * NB + (lo >> 5)], 1);
}

// ---------------- bin exclusive scan (single block) ----------------
__global__ void __launch_bounds__(1024) k_binscan() {
    __shared__ int s[1024];
    int tid = threadIdx.x;
    s[tid] = (tid < NBT) ? g_bincnt[tid] : 0;
    __syncthreads();
    for (int off = 1; off < 1024; off <<= 1) {
        int v = (tid >= off) ? s[tid - off] : 0;
        __syncthreads();
        s[tid] += v;
        __syncthreads();
    }
    if (tid <= NBT) g_binoff[tid] = (tid == 0) ? 0 : s[tid - 1];
}

// ---------------- scatter queries into bins ----------------
__global__ void k_scatter() {
    int i = blockIdx.x * 256 + threadIdx.x;
    int b = i >> 12;
    int gbin = b * NB + (g_t[i] >> 5);
    int pos = g_binoff[gbin] + atomicAdd(&g_bincur[gbin], 1);
    g_qlist[pos] = i;
}

// ---------------- chunk sums (32-element chunks) ----------------
__global__ void __launch_bounds__(256) k_chunksum() {
    int bx = blockIdx.x;
    int b = bx >> 7, c = bx & 127;
    int d = threadIdx.x;
    __shared__ float ev[32];
    __shared__ int   sord[32];
    int base = b * LL + c * 32;
    if (d < 32) {
        float e = expf(-g_ksort[base + d]);
        ev[d] = e;
        sord[d] = g_ord[base + d];
        #pragma unroll
        for (int o = 16; o; o >>= 1) e += __shfl_down_sync(0xffffffffu, e, o);
        if (d == 0) g_chE[b * NB + c] = e;
    }
    __syncthreads();
    float sEV = 0.f, sV = 0.f;
    #pragma unroll 4
    for (int i = 0; i < 32; i++) {
        float v = g_V[(size_t)(b * LL + sord[i]) * DD + d];
        sEV = fmaf(ev[i], v, sEV);
        sV += v;
    }
    g_chEV[(b * NB + c) * DD + d] = sEV;
    g_chV [(b * NB + c) * DD + d] = sV;
}

// ---------------- exclusive scan over chunk sums (+ totals at idx 128) ----------------
__global__ void __launch_bounds__(256) k_chunkscan() {
    int b = blockIdx.x, d = threadIdx.x;
    float runEV = 0.f, runV = 0.f;
    #pragma unroll 8
    for (int c = 0; c < 128; c++) {
        int idx = (b * NB + c) * DD + d;
        float t1 = g_chEV[idx]; g_chEV[idx] = runEV; runEV += t1;
        float t2 = g_chV[idx];  g_chV[idx]  = runV;  runV  += t2;
    }
    g_chEV[(b * NB + 128) * DD + d] = runEV;
    g_chV [(b * NB + 128) * DD + d] = runV;
    if (d == 0) {
        float run = 0.f;
        #pragma unroll 8
        for (int c = 0; c < 128; c++) {
            float t = g_chE[b * NB + c]; g_chE[b * NB + c] = run; run += t;
        }
        g_chE[b * NB + 128] = run;
    }
}

// ---------------- grouped output: one block per (batch, chunk-bin) ----------------
__global__ void __launch_bounds__(256) k_gout(float* __restrict__ out) {
    extern __shared__ float dsm[];
    float* pEV = dsm;               // [33][256]
    float* pV  = dsm + 33 * 256;    // [33][256]
    __shared__ float ev[32];
    __shared__ int   sord[32];
    __shared__ float pe[33];
    int gbin = blockIdx.x;
    int b = gbin / NB, c = gbin - b * NB;
    int q0 = g_binoff[gbin], q1 = g_binoff[gbin + 1];
    if (q0 == q1) return;
    int d = threadIdx.x;
    int csize = (c < 128) ? 32 : 0;
    if (d < 32 && csize) {
        ev[d]   = expf(-g_ksort[b * LL + c * 32 + d]);
        sord[d] = g_ord[b * LL + c * 32 + d];
    }
    __syncthreads();
    // prefix base = inter-chunk exclusive prefix
    pEV[d] = g_chEV[(b * NB + c) * DD + d];
    pV [d] = g_chV [(b * NB + c) * DD + d];
    if (csize) {
        float vr[32];
        #pragma unroll
        for (int i = 0; i < 32; i++)
            vr[i] = g_V[(size_t)(b * LL + sord[i]) * DD + d];
        #pragma unroll
        for (int i = 0; i < 32; i++) {
            pEV[(i + 1) * 256 + d] = fmaf(ev[i], vr[i], pEV[i * 256 + d]);
            pV [(i + 1) * 256 + d] = pV[i * 256 + d] + vr[i];
        }
    }
    if (d == 0) {
        float a = g_chE[b * NB + c];
        pe[0] = a;
        for (int i = 0; i < csize; i++) { a += ev[i]; pe[i + 1] = a; }
    }
    float TVd = g_chV[(b * NB + 128) * DD + d];
    __syncthreads();
    for (int p = q0; p < q1; p++) {
        int qi = g_qlist[p];
        int t = g_t[qi];
        int rloc = t - c * 32;
        float E = expf(g_qs[qi]);
        float den = fmaf(E, pe[rloc], (float)(LL - t));
        float num = fmaf(E, pEV[rloc * 256 + d], TVd - pV[rloc * 256 + d]);
        out[(size_t)qi * DD + d] = num / den;
    }
}

// ---------------- launch ----------------
extern "C" void kernel_launch(void* const* d_in, const int* in_sizes, int n_in,
                              void* d_out, int out_size) {
    const float* x   = (const float*)d_in[0];
    const float* Wq  = (const float*)d_in[1];
    const float* Wk  = (const float*)d_in[2];
    const float* Wv  = (const float*)d_in[3];
    const float* w   = (const float*)d_in[4];
    const float* bm  = (const float*)d_in[5];
    float* out = (float*)d_out;

    static int smem_set = 0;
    if (!smem_set) {
        cudaFuncSetAttribute(k_gout, cudaFuncAttributeMaxDynamicSharedMemorySize,
                             2 * 33 * 256 * (int)sizeof(float));
        smem_set = 1;
    }

    k_uvec<<<2, 1024>>>(Wq, Wk, w);
    k_qk<<<BL / 64, 256>>>(x, bm);
    k_vgemm<<<dim3(BL / 128, DD / 128), 256>>>(x, Wv);
    k_tsort<<<BL / 256, 256>>>();
    k_rank2<<<dim3(64, 16), 256>>>();
    k_ranksum<<<BL / 256, 256>>>();
    k_zero<<<1, 1024>>>();
    k_thresh_hist<<<BL / 256, 256>>>();
    k_binscan<<<1, 1024>>>();
    k_scatter<<<BL / 256, 256>>>();
    k_chunksum<<<BB * 128, 256>>>();
    k_chunkscan<<<BB, 256>>>();
    k_gout<<<NBT, 256, 2 * 33 * 256 * sizeof(float)>>>(out);
}

// round 11
// speedup vs baseline: 2.3673x; 1.0404x over previous
#include <cuda_runtime.h>
#include <cuda_bf16.h>
#include <cstdint>

#define BB 4
#define LL 4096
#define DD 256
#define BL (BB*LL)
#define NB 129          // chunks per batch (128) + overflow bin (t=4096)
#define NBT (BB*NB)

// ---------------- static scratch ----------------
__device__ float g_V[BL*DD];
__device__ float g_uq[DD];
__device__ float g_uk[DD];
__device__ float g_qs[BL];
__device__ float g_ks[BL];
__device__ float g_ksort[BL];
__device__ int   g_ord[BL];
__device__ int   g_t[BL];
__device__ unsigned long long g_tk[BL];   // per-tile sorted packed keys
__device__ int   g_rpart[16*BL];          // per-tile k-rank partials
__device__ int   g_rpartq[16*BL];         // per-tile q-threshold partials
__device__ float g_chE[BB*NB];
__device__ float g_chEV[BB*NB*DD];
__device__ float g_chV[BB*NB*DD];

__device__ __forceinline__ uint32_t fmap(float f) {
    uint32_t u = __float_as_uint(f);
    return ((int)u < 0) ? ~u : (u | 0x80000000u);
}

// ---------------- uq = Wq^T w, uk = Wk^T w ----------------
__global__ void __launch_bounds__(1024) k_uvec(const float* __restrict__ Wq,
                                               const float* __restrict__ Wk,
                                               const float* __restrict__ w) {
    __shared__ float part[4][DD];
    const float* W = (blockIdx.x == 0) ? Wq : Wk;
    int d = threadIdx.x & 255, ec = threadIdx.x >> 8;
    float s = 0.f;
    #pragma unroll 8
    for (int e = ec * 64; e < ec * 64 + 64; e++)
        s = fmaf(W[e * DD + d], w[e], s);
    part[ec][d] = s;
    __syncthreads();
    if (ec == 0) {
        float r = part[0][d] + part[1][d] + part[2][d] + part[3][d];
        if (blockIdx.x == 0) g_uq[d] = r; else g_uk[d] = r;
    }
}

// ---------------- per-row scalar q/k ----------------
__global__ void __launch_bounds__(256) k_qk(const float* __restrict__ x,
                                            const float* __restrict__ bptr) {
    __shared__ float suq[DD], suk[DD];
    suq[threadIdx.x] = g_uq[threadIdx.x];
    suk[threadIdx.x] = g_uk[threadIdx.x];
    __syncthreads();
    int warp = threadIdx.x >> 5, lane = threadIdx.x & 31;
    float bias = bptr[0];
    #pragma unroll
    for (int r = 0; r < 8; r++) {
        int m = blockIdx.x * 64 + warp * 8 + r;
        const float* xr = x + (size_t)m * DD;
        float4 xa = *(const float4*)&xr[lane * 4];
        float4 xb = *(const float4*)&xr[128 + lane * 4];
        int da = lane * 4, db = 128 + lane * 4;
        float sq = xa.x * suq[da] + xa.y * suq[da+1] + xa.z * suq[da+2] + xa.w * suq[da+3]
                 + xb.x * suq[db] + xb.y * suq[db+1] + xb.z * suq[db+2] + xb.w * suq[db+3];
        float sk = xa.x * suk[da] + xa.y * suk[da+1] + xa.z * suk[da+2] + xa.w * suk[da+3]
                 + xb.x * suk[db] + xb.y * suk[db+1] + xb.z * suk[db+2] + xb.w * suk[db+3];
        #pragma unroll
        for (int o = 16; o; o >>= 1) {
            sq += __shfl_down_sync(0xffffffffu, sq, o);
            sk += __shfl_down_sync(0xffffffffu, sk, o);
        }
        if (lane == 0) { g_qs[m] = sq + bias; g_ks[m] = sk; }
    }
}

// ---------------- V = x @ Wv^T : mma.sync bf16 3-pass split ----------------
#define PITCH 36
__device__ __forceinline__ void mma_bf16(float* d, const uint32_t* a, const uint32_t* b) {
    asm volatile("mma.sync.aligned.m16n8k16.row.col.f32.bf16.bf16.f32 "
        "{%0,%1,%2,%3}, {%4,%5,%6,%7}, {%8,%9}, {%0,%1,%2,%3};"
        : "+f"(d[0]), "+f"(d[1]), "+f"(d[2]), "+f"(d[3])
        : "r"(a[0]), "r"(a[1]), "r"(a[2]), "r"(a[3]), "r"(b[0]), "r"(b[1]));
}

__global__ void __launch_bounds__(256) k_vgemm(const float* __restrict__ x,
                                               const float* __restrict__ Wv) {
    __shared__ __nv_bfloat16 sAh[128][PITCH], sAl[128][PITCH];
    __shared__ __nv_bfloat16 sBh[128][PITCH], sBl[128][PITCH];
    int tid = threadIdx.x, wid = tid >> 5, lane = tid & 31;
    int g = lane >> 2, t4 = lane & 3;
    int wr = wid >> 2, wc = wid & 3;
    int m0 = blockIdx.x * 128, n0 = blockIdx.y * 128;

    float acc[4][4][4];
    #pragma unroll
    for (int mt = 0; mt < 4; mt++)
        #pragma unroll
        for (int nt = 0; nt < 4; nt++)
            #pragma unroll
            for (int e = 0; e < 4; e++) acc[mt][nt][e] = 0.f;

    for (int k0 = 0; k0 < DD; k0 += 32) {
        #pragma unroll
        for (int p = 0; p < 8; p++) {
            int s = p * 256 + tid;
            int row = (s & 1023) >> 3, kq = s & 7;
            const float* src = (s < 1024)
                ? &x [(size_t)(m0 + row) * DD + k0 + kq * 4]
                : &Wv[(size_t)(n0 + row) * DD + k0 + kq * 4];
            float4 v = *(const float4*)src;
            __nv_bfloat162 h0 = __floats2bfloat162_rn(v.x, v.y);
            __nv_bfloat162 h1 = __floats2bfloat162_rn(v.z, v.w);
            __nv_bfloat162 l0 = __floats2bfloat162_rn(v.x - __low2float(h0),
                                                      v.y - __high2float(h0));
            __nv_bfloat162 l1 = __floats2bfloat162_rn(v.z - __low2float(h1),
                                                      v.w - __high2float(h1));
            __nv_bfloat16* dh = (s < 1024) ? &sAh[row][kq * 4] : &sBh[row][kq * 4];
            __nv_bfloat16* dl = (s < 1024) ? &sAl[row][kq * 4] : &sBl[row][kq * 4];
            *(uint2*)dh = make_uint2(*(uint32_t*)&h0, *(uint32_t*)&h1);
            *(uint2*)dl = make_uint2(*(uint32_t*)&l0, *(uint32_t*)&l1);
        }
        __syncthreads();
        #pragma unroll
        for (int ks = 0; ks < 32; ks += 16) {
            uint32_t ah[4][4], al[4][4], bh[4][2], bl[4][2];
            #pragma unroll
            for (int mt = 0; mt < 4; mt++) {
                int rb = wr * 64 + mt * 16;
                int kc = ks + 2 * t4;
                ah[mt][0] = *(uint32_t*)&sAh[rb + g    ][kc];
                ah[mt][1] = *(uint32_t*)&sAh[rb + g + 8][kc];
                ah[mt][2] = *(uint32_t*)&sAh[rb + g    ][kc + 8];
                ah[mt][3] = *(uint32_t*)&sAh[rb + g + 8][kc + 8];
                al[mt][0] = *(uint32_t*)&sAl[rb + g    ][kc];
                al[mt][1] = *(uint32_t*)&sAl[rb + g + 8][kc];
                al[mt][2] = *(uint32_t*)&sAl[rb + g    ][kc + 8];
                al[mt][3] = *(uint32_t*)&sAl[rb + g + 8][kc + 8];
            }
            #pragma unroll
            for (int nt = 0; nt < 4; nt++) {
                int nb = wc * 32 + nt * 8;
                int kc = ks + 2 * t4;
                bh[nt][0] = *(uint32_t*)&sBh[nb + g][kc];
                bh[nt][1] = *(uint32_t*)&sBh[nb + g][kc + 8];
                bl[nt][0] = *(uint32_t*)&sBl[nb + g][kc];
                bl[nt][1] = *(uint32_t*)&sBl[nb + g][kc + 8];
            }
            #pragma unroll
            for (int mt = 0; mt < 4; mt++)
                #pragma unroll
                for (int nt = 0; nt < 4; nt++) {
                    mma_bf16(acc[mt][nt], ah[mt], bh[nt]);
                    mma_bf16(acc[mt][nt], ah[mt], bl[nt]);
                    mma_bf16(acc[mt][nt], al[mt], bh[nt]);
                }
        }
        __syncthreads();
    }
    #pragma unroll
    for (int mt = 0; mt < 4; mt++)
        #pragma unroll
        for (int nt = 0; nt < 4; nt++) {
            int m = m0 + wr * 64 + mt * 16 + g;
            int n = n0 + wc * 32 + nt * 8 + 2 * t4;
            *(float2*)&g_V[(size_t)m * DD + n] =
                make_float2(acc[mt][nt][0], acc[mt][nt][1]);
            *(float2*)&g_V[(size_t)(m + 8) * DD + n] =
                make_float2(acc[mt][nt][2], acc[mt][nt][3]);
        }
}

// ---------------- sort 256-key tiles (bitonic, u64 packed keys) ----------------
__global__ void __launch_bounds__(256) k_tsort() {
    __shared__ unsigned long long sk[256];
    int base = blockIdx.x * 256;
    int tid = threadIdx.x;
    int jloc = (base + tid) & (LL - 1);
    sk[tid] = ((unsigned long long)fmap(g_ks[base + tid]) << 12) | (unsigned)jloc;
    __syncthreads();
    for (int k = 2; k <= 256; k <<= 1) {
        for (int j = k >> 1; j > 0; j >>= 1) {
            int ixj = tid ^ j;
            if (ixj > tid) {
                bool asc = ((tid & k) == 0);
                unsigned long long a = sk[tid], c = sk[ixj];
                if (asc ? (a > c) : (a < c)) { sk[tid] = c; sk[ixj] = a; }
            }
            __syncthreads();
        }
    }
    g_tk[base + tid] = sk[tid];
}

// ---------------- per-tile lower_bounds: k-rank AND q-threshold ----------------
__device__ __forceinline__ int lb256(const unsigned long long* st, unsigned long long key) {
    if (st[255] < key) return 256;
    int pos = 0;
    #pragma unroll
    for (int step = 128; step; step >>= 1)
        if (st[pos + step - 1] < key) pos += step;
    return pos;
}

__global__ void __launch_bounds__(256) k_rank2() {
    __shared__ unsigned long long st[256];
    int tile = blockIdx.x;            // 0..63
    int batch = tile >> 4;
    int tid = threadIdx.x;
    st[tid] = g_tk[tile * 256 + tid];
    int j = batch * LL + blockIdx.y * 256 + tid;
    unsigned long long kj = ((unsigned long long)fmap(g_ks[j]) << 12)
                          | (unsigned)(j & (LL - 1));
    unsigned long long qj = ((unsigned long long)fmap(g_qs[j]) << 12);
    __syncthreads();
    g_rpart [(tile & 15) * BL + j] = lb256(st, kj);
    g_rpartq[(tile & 15) * BL + j] = lb256(st, qj);  // = #{k < q} in this tile
}

// ---------------- final rank: scatter sorted keys + threshold per query ----------------
__global__ void k_ranksum() {
    int j = blockIdx.x * 256 + threadIdx.x;
    int sumk = 0, sumq = 0;
    #pragma unroll
    for (int ic = 0; ic < 16; ic++) {
        sumk += g_rpart [ic * BL + j];
        sumq += g_rpartq[ic * BL + j];
    }
    int b = j >> 12;
    g_ksort[b * LL + sumk] = g_ks[j];
    g_ord[b * LL + sumk]   = j & (LL - 1);
    g_t[j] = sumq;
}

// ---------------- chunk sums (32-element chunks) ----------------
__global__ void __launch_bounds__(256) k_chunksum() {
    int bx = blockIdx.x;
    int b = bx >> 7, c = bx & 127;
    int d = threadIdx.x;
    __shared__ float ev[32];
    __shared__ int   sord[32];
    int base = b * LL + c * 32;
    if (d < 32) {
        float e = expf(-g_ksort[base + d]);
        ev[d] = e;
        sord[d] = g_ord[base + d];
        #pragma unroll
        for (int o = 16; o; o >>= 1) e += __shfl_down_sync(0xffffffffu, e, o);
        if (d == 0) g_chE[b * NB + c] = e;
    }
    __syncthreads();
    float sEV = 0.f, sV = 0.f;
    #pragma unroll 4
    for (int i = 0; i < 32; i++) {
        float v = g_V[(size_t)(b * LL + sord[i]) * DD + d];
        sEV = fmaf(ev[i], v, sEV);
        sV += v;
    }
    g_chEV[(b * NB + c) * DD + d] = sEV;
    g_chV [(b * NB + c) * DD + d] = sV;
}

// ---------------- exclusive scan over chunk sums (+ totals at idx 128) ----------------
__global__ void __launch_bounds__(256) k_chunkscan() {
    int b = blockIdx.x, d = threadIdx.x;
    float runEV = 0.f, runV = 0.f;
    #pragma unroll 8
    for (int c = 0; c < 128; c++) {
        int idx = (b * NB + c) * DD + d;
        float t1 = g_chEV[idx]; g_chEV[idx] = runEV; runEV += t1;
        float t2 = g_chV[idx];  g_chV[idx]  = runV;  runV  += t2;
    }
    g_chEV[(b * NB + 128) * DD + d] = runEV;
    g_chV [(b * NB + 128) * DD + d] = runV;
    if (d == 0) {
        float run = 0.f;
        #pragma unroll 8
        for (int c = 0; c < 128; c++) {
            float t = g_chE[b * NB + c]; g_chE[b * NB + c] = run; run += t;
        }
        g_chE[b * NB + 128] = run;
    }
}

// ---------------- grouped output: one block per (batch, chunk) bin ----------------
// Finds its own queries by scanning g_t (no global binning kernels needed).
__global__ void __launch_bounds__(256) k_gout(float* __restrict__ out) {
    extern __shared__ float dsm[];
    float* pEV = dsm;               // [33][256]
    float* pV  = dsm + 33 * 256;    // [33][256]
    __shared__ float ev[32];
    __shared__ int   sord[32];
    __shared__ float pe[33];
    __shared__ int   slist[4096];
    __shared__ int   scount;
    int gbin = blockIdx.x;
    int b = gbin / NB, c = gbin - b * NB;
    int d = threadIdx.x;
    if (d == 0) scount = 0;
    int csize = (c < 128) ? 32 : 0;
    if (d < 32 && csize) {
        ev[d]   = expf(-g_ksort[b * LL + c * 32 + d]);
        sord[d] = g_ord[b * LL + c * 32 + d];
    }
    __syncthreads();
    // gather this bin's queries from g_t
    #pragma unroll 4
    for (int idx = d; idx < LL; idx += 256) {
        int t = g_t[b * LL + idx];
        if ((t >> 5) == c) slist[atomicAdd(&scount, 1)] = idx;
    }
    __syncthreads();
    int nq = scount;
    if (nq == 0) return;
    // build within-chunk prefixes on top of inter-chunk exclusive base
    pEV[d] = g_chEV[(b * NB + c) * DD + d];
    pV [d] = g_chV [(b * NB + c) * DD + d];
    if (csize) {
        float vr[32];
        #pragma unroll
        for (int i = 0; i < 32; i++)
            vr[i] = g_V[(size_t)(b * LL + sord[i]) * DD + d];
        #pragma unroll
        for (int i = 0; i < 32; i++) {
            pEV[(i + 1) * 256 + d] = fmaf(ev[i], vr[i], pEV[i * 256 + d]);
            pV [(i + 1) * 256 + d] = pV[i * 256 + d] + vr[i];
        }
    }
    if (d == 0) {
        float a = g_chE[b * NB + c];
        pe[0] = a;
        for (int i = 0; i < csize; i++) { a += ev[i]; pe[i + 1] = a; }
    }
    float TVd = g_chV[(b * NB + 128) * DD + d];
    __syncthreads();
    for (int p = 0; p < nq; p++) {
        int ql = slist[p];
        int qi = b * LL + ql;
        int t = g_t[qi];
        int rloc = t - c * 32;
        float E = expf(g_qs[qi]);
        float den = fmaf(E, pe[rloc], (float)(LL - t));
        float num = fmaf(E, pEV[rloc * 256 + d], TVd - pV[rloc * 256 + d]);
        out[(size_t)qi * DD + d] = num / den;
    }
}

// ---------------- launch ----------------
extern "C" void kernel_launch(void* const* d_in, const int* in_sizes, int n_in,
                              void* d_out, int out_size) {
    const float* x   = (const float*)d_in[0];
    const float* Wq  = (const float*)d_in[1];
    const float* Wk  = (const float*)d_in[2];
    const float* Wv  = (const float*)d_in[3];
    const float* w   = (const float*)d_in[4];
    const float* bm  = (const float*)d_in[5];
    float* out = (float*)d_out;

    static int smem_set = 0;
    if (!smem_set) {
        cudaFuncSetAttribute(k_gout, cudaFuncAttributeMaxDynamicSharedMemorySize,
                             2 * 33 * 256 * (int)sizeof(float));
        smem_set = 1;
    }

    k_uvec<<<2, 1024>>>(Wq, Wk, w);
    k_qk<<<BL / 64, 256>>>(x, bm);
    k_vgemm<<<dim3(BL / 128, DD / 128), 256>>>(x, Wv);
    k_tsort<<<BL / 256, 256>>>();
    k_rank2<<<dim3(64, 16), 256>>>();
    k_ranksum<<<BL / 256, 256>>>();
    k_chunksum<<<BB * 128, 256>>>();
    k_chunkscan<<<BB, 256>>>();
    k_gout<<<NBT, 256, 2 * 33 * 256 * sizeof(float)>>>(out);
}

// round 12
// speedup vs baseline: 2.6081x; 1.1018x over previous
#include <cuda_runtime.h>
#include <cuda_bf16.h>
#include <cstdint>

#define BB 4
#define LL 4096
#define DD 256
#define BL (BB*LL)
#define NB 129          // chunks per batch (128) + overflow bin (t=4096)
#define NBT (BB*NB)

// ---------------- static scratch ----------------
__device__ float g_V[BL*DD];
__device__ float g_uq[DD];
__device__ float g_uk[DD];
__device__ float g_qs[BL];
__device__ float g_ks[BL];
__device__ float g_ksort[BL];
__device__ int   g_ord[BL];
__device__ int   g_t[BL];
__device__ unsigned long long g_tk[BL];   // per-tile sorted packed keys
__device__ int   g_rpart[16*BL];          // per-tile k-rank partials
__device__ int   g_rpartq[16*BL];         // per-tile q-threshold partials
__device__ float g_chE[BB*NB];
__device__ float g_chEV[BB*NB*DD];
__device__ float g_chV[BB*NB*DD];

__device__ __forceinline__ uint32_t fmap(float f) {
    uint32_t u = __float_as_uint(f);
    return ((int)u < 0) ? ~u : (u | 0x80000000u);
}

// ---------------- uq = Wq^T w, uk = Wk^T w ----------------
__global__ void __launch_bounds__(1024) k_uvec(const float* __restrict__ Wq,
                                               const float* __restrict__ Wk,
                                               const float* __restrict__ w) {
    __shared__ float part[4][DD];
    const float* W = (blockIdx.x == 0) ? Wq : Wk;
    int d = threadIdx.x & 255, ec = threadIdx.x >> 8;
    float s = 0.f;
    #pragma unroll 8
    for (int e = ec * 64; e < ec * 64 + 64; e++)
        s = fmaf(W[e * DD + d], w[e], s);
    part[ec][d] = s;
    __syncthreads();
    if (ec == 0) {
        float r = part[0][d] + part[1][d] + part[2][d] + part[3][d];
        if (blockIdx.x == 0) g_uq[d] = r; else g_uk[d] = r;
    }
}

// ---------------- per-row scalar q/k ----------------
__global__ void __launch_bounds__(256) k_qk(const float* __restrict__ x,
                                            const float* __restrict__ bptr) {
    __shared__ float suq[DD], suk[DD];
    suq[threadIdx.x] = g_uq[threadIdx.x];
    suk[threadIdx.x] = g_uk[threadIdx.x];
    __syncthreads();
    int warp = threadIdx.x >> 5, lane = threadIdx.x & 31;
    float bias = bptr[0];
    #pragma unroll
    for (int r = 0; r < 8; r++) {
        int m = blockIdx.x * 64 + warp * 8 + r;
        const float* xr = x + (size_t)m * DD;
        float4 xa = *(const float4*)&xr[lane * 4];
        float4 xb = *(const float4*)&xr[128 + lane * 4];
        int da = lane * 4, db = 128 + lane * 4;
        float sq = xa.x * suq[da] + xa.y * suq[da+1] + xa.z * suq[da+2] + xa.w * suq[da+3]
                 + xb.x * suq[db] + xb.y * suq[db+1] + xb.z * suq[db+2] + xb.w * suq[db+3];
        float sk = xa.x * suk[da] + xa.y * suk[da+1] + xa.z * suk[da+2] + xa.w * suk[da+3]
                 + xb.x * suk[db] + xb.y * suk[db+1] + xb.z * suk[db+2] + xb.w * suk[db+3];
        #pragma unroll
        for (int o = 16; o; o >>= 1) {
            sq += __shfl_down_sync(0xffffffffu, sq, o);
            sk += __shfl_down_sync(0xffffffffu, sk, o);
        }
        if (lane == 0) { g_qs[m] = sq + bias; g_ks[m] = sk; }
    }
}

// ---------------- V = x @ Wv^T : mma.sync bf16 3-pass split ----------------
#define PITCH 36
__device__ __forceinline__ void mma_bf16(float* d, const uint32_t* a, const uint32_t* b) {
    asm volatile("mma.sync.aligned.m16n8k16.row.col.f32.bf16.bf16.f32 "
        "{%0,%1,%2,%3}, {%4,%5,%6,%7}, {%8,%9}, {%0,%1,%2,%3};"
        : "+f"(d[0]), "+f"(d[1]), "+f"(d[2]), "+f"(d[3])
        : "r"(a[0]), "r"(a[1]), "r"(a[2]), "r"(a[3]), "r"(b[0]), "r"(b[1]));
}

__global__ void __launch_bounds__(256) k_vgemm(const float* __restrict__ x,
                                               const float* __restrict__ Wv) {
    __shared__ __nv_bfloat16 sAh[128][PITCH], sAl[128][PITCH];
    __shared__ __nv_bfloat16 sBh[128][PITCH], sBl[128][PITCH];
    int tid = threadIdx.x, wid = tid >> 5, lane = tid & 31;
    int g = lane >> 2, t4 = lane & 3;
    int wr = wid >> 2, wc = wid & 3;
    int m0 = blockIdx.x * 128, n0 = blockIdx.y * 128;

    float acc[4][4][4];
    #pragma unroll
    for (int mt = 0; mt < 4; mt++)
        #pragma unroll
        for (int nt = 0; nt < 4; nt++)
            #pragma unroll
            for (int e = 0; e < 4; e++) acc[mt][nt][e] = 0.f;

    for (int k0 = 0; k0 < DD; k0 += 32) {
        #pragma unroll
        for (int p = 0; p < 8; p++) {
            int s = p * 256 + tid;
            int row = (s & 1023) >> 3, kq = s & 7;
            const float* src = (s < 1024)
                ? &x [(size_t)(m0 + row) * DD + k0 + kq * 4]
                : &Wv[(size_t)(n0 + row) * DD + k0 + kq * 4];
            float4 v = *(const float4*)src;
            __nv_bfloat162 h0 = __floats2bfloat162_rn(v.x, v.y);
            __nv_bfloat162 h1 = __floats2bfloat162_rn(v.z, v.w);
            __nv_bfloat162 l0 = __floats2bfloat162_rn(v.x - __low2float(h0),
                                                      v.y - __high2float(h0));
            __nv_bfloat162 l1 = __floats2bfloat162_rn(v.z - __low2float(h1),
                                                      v.w - __high2float(h1));
            __nv_bfloat16* dh = (s < 1024) ? &sAh[row][kq * 4] : &sBh[row][kq * 4];
            __nv_bfloat16* dl = (s < 1024) ? &sAl[row][kq * 4] : &sBl[row][kq * 4];
            *(uint2*)dh = make_uint2(*(uint32_t*)&h0, *(uint32_t*)&h1);
            *(uint2*)dl = make_uint2(*(uint32_t*)&l0, *(uint32_t*)&l1);
        }
        __syncthreads();
        #pragma unroll
        for (int ks = 0; ks < 32; ks += 16) {
            uint32_t ah[4][4], al[4][4], bh[4][2], bl[4][2];
            #pragma unroll
            for (int mt = 0; mt < 4; mt++) {
                int rb = wr * 64 + mt * 16;
                int kc = ks + 2 * t4;
                ah[mt][0] = *(uint32_t*)&sAh[rb + g    ][kc];
                ah[mt][1] = *(uint32_t*)&sAh[rb + g + 8][kc];
                ah[mt][2] = *(uint32_t*)&sAh[rb + g    ][kc + 8];
                ah[mt][3] = *(uint32_t*)&sAh[rb + g + 8][kc + 8];
                al[mt][0] = *(uint32_t*)&sAl[rb + g    ][kc];
                al[mt][1] = *(uint32_t*)&sAl[rb + g + 8][kc];
                al[mt][2] = *(uint32_t*)&sAl[rb + g    ][kc + 8];
                al[mt][3] = *(uint32_t*)&sAl[rb + g + 8][kc + 8];
            }
            #pragma unroll
            for (int nt = 0; nt < 4; nt++) {
                int nb = wc * 32 + nt * 8;
                int kc = ks + 2 * t4;
                bh[nt][0] = *(uint32_t*)&sBh[nb + g][kc];
                bh[nt][1] = *(uint32_t*)&sBh[nb + g][kc + 8];
                bl[nt][0] = *(uint32_t*)&sBl[nb + g][kc];
                bl[nt][1] = *(uint32_t*)&sBl[nb + g][kc + 8];
            }
            #pragma unroll
            for (int mt = 0; mt < 4; mt++)
                #pragma unroll
                for (int nt = 0; nt < 4; nt++) {
                    mma_bf16(acc[mt][nt], ah[mt], bh[nt]);
                    mma_bf16(acc[mt][nt], ah[mt], bl[nt]);
                    mma_bf16(acc[mt][nt], al[mt], bh[nt]);
                }
        }
        __syncthreads();
    }
    #pragma unroll
    for (int mt = 0; mt < 4; mt++)
        #pragma unroll
        for (int nt = 0; nt < 4; nt++) {
            int m = m0 + wr * 64 + mt * 16 + g;
            int n = n0 + wc * 32 + nt * 8 + 2 * t4;
            *(float2*)&g_V[(size_t)m * DD + n] =
                make_float2(acc[mt][nt][0], acc[mt][nt][1]);
            *(float2*)&g_V[(size_t)(m + 8) * DD + n] =
                make_float2(acc[mt][nt][2], acc[mt][nt][3]);
        }
}

// ---------------- sort 256-key tiles (bitonic, u64 packed keys) ----------------
__global__ void __launch_bounds__(256) k_tsort() {
    __shared__ unsigned long long sk[256];
    int base = blockIdx.x * 256;
    int tid = threadIdx.x;
    int jloc = (base + tid) & (LL - 1);
    sk[tid] = ((unsigned long long)fmap(g_ks[base + tid]) << 12) | (unsigned)jloc;
    __syncthreads();
    for (int k = 2; k <= 256; k <<= 1) {
        for (int j = k >> 1; j > 0; j >>= 1) {
            int ixj = tid ^ j;
            if (ixj > tid) {
                bool asc = ((tid & k) == 0);
                unsigned long long a = sk[tid], c = sk[ixj];
                if (asc ? (a > c) : (a < c)) { sk[tid] = c; sk[ixj] = a; }
            }
            __syncthreads();
        }
    }
    g_tk[base + tid] = sk[tid];
}

// ---------------- per-tile lower_bounds: k-rank AND q-threshold ----------------
__device__ __forceinline__ int lb256(const unsigned long long* st, unsigned long long key) {
    if (st[255] < key) return 256;
    int pos = 0;
    #pragma unroll
    for (int step = 128; step; step >>= 1)
        if (st[pos + step - 1] < key) pos += step;
    return pos;
}

__global__ void __launch_bounds__(256) k_rank2() {
    __shared__ unsigned long long st[256];
    int tile = blockIdx.x;            // 0..63
    int batch = tile >> 4;
    int tid = threadIdx.x;
    st[tid] = g_tk[tile * 256 + tid];
    int j = batch * LL + blockIdx.y * 256 + tid;
    unsigned long long kj = ((unsigned long long)fmap(g_ks[j]) << 12)
                          | (unsigned)(j & (LL - 1));
    unsigned long long qj = ((unsigned long long)fmap(g_qs[j]) << 12);
    __syncthreads();
    g_rpart [(tile & 15) * BL + j] = lb256(st, kj);
    g_rpartq[(tile & 15) * BL + j] = lb256(st, qj);  // = #{k < q} in this tile
}

// ---------------- final rank: scatter sorted keys + threshold per query ----------------
__global__ void k_ranksum() {
    int j = blockIdx.x * 256 + threadIdx.x;
    int sumk = 0, sumq = 0;
    #pragma unroll
    for (int ic = 0; ic < 16; ic++) {
        sumk += g_rpart [ic * BL + j];
        sumq += g_rpartq[ic * BL + j];
    }
    int b = j >> 12;
    g_ksort[b * LL + sumk] = g_ks[j];
    g_ord[b * LL + sumk]   = j & (LL - 1);
    g_t[j] = sumq;
}

// ---------------- chunk sums (32-element chunks) ----------------
__global__ void __launch_bounds__(256) k_chunksum() {
    int bx = blockIdx.x;
    int b = bx >> 7, c = bx & 127;
    int d = threadIdx.x;
    __shared__ float ev[32];
    __shared__ int   sord[32];
    int base = b * LL + c * 32;
    if (d < 32) {
        float e = expf(-g_ksort[base + d]);
        ev[d] = e;
        sord[d] = g_ord[base + d];
        #pragma unroll
        for (int o = 16; o; o >>= 1) e += __shfl_down_sync(0xffffffffu, e, o);
        if (d == 0) g_chE[b * NB + c] = e;
    }
    __syncthreads();
    float sEV = 0.f, sV = 0.f;
    #pragma unroll 4
    for (int i = 0; i < 32; i++) {
        float v = g_V[(size_t)(b * LL + sord[i]) * DD + d];
        sEV = fmaf(ev[i], v, sEV);
        sV += v;
    }
    g_chEV[(b * NB + c) * DD + d] = sEV;
    g_chV [(b * NB + c) * DD + d] = sV;
}

// ---------------- exclusive scan over chunk sums (+ totals at idx 128) ----------------
__global__ void __launch_bounds__(256) k_chunkscan() {
    int b = blockIdx.x, d = threadIdx.x;
    float runEV = 0.f, runV = 0.f;
    #pragma unroll 8
    for (int c = 0; c < 128; c++) {
        int idx = (b * NB + c) * DD + d;
        float t1 = g_chEV[idx]; g_chEV[idx] = runEV; runEV += t1;
        float t2 = g_chV[idx];  g_chV[idx]  = runV;  runV  += t2;
    }
    g_chEV[(b * NB + 128) * DD + d] = runEV;
    g_chV [(b * NB + 128) * DD + d] = runV;
    if (d == 0) {
        float run = 0.f;
        #pragma unroll 8
        for (int c = 0; c < 128; c++) {
            float t = g_chE[b * NB + c]; g_chE[b * NB + c] = run; run += t;
        }
        g_chE[b * NB + 128] = run;
    }
}

// ---------------- grouped output: one block per (batch, chunk) bin ----------------
__global__ void __launch_bounds__(256) k_gout(float* __restrict__ out) {
    extern __shared__ float dsm[];
    float* pEV = dsm;               // [33][256]
    float* pV  = dsm + 33 * 256;    // [33][256]
    __shared__ float ev[32];
    __shared__ int   sord[32];
    __shared__ float pe[33];
    __shared__ int   slist[4096];
    __shared__ int   scount;
    int gbin = blockIdx.x;
    int b = gbin / NB, c = gbin - b * NB;
    int d = threadIdx.x;
    if (d == 0) scount = 0;
    int csize = (c < 128) ? 32 : 0;
    if (d < 32 && csize) {
        ev[d]   = expf(-g_ksort[b * LL + c * 32 + d]);
        sord[d] = g_ord[b * LL + c * 32 + d];
    }
    __syncthreads();
    // gather this bin's queries from g_t
    #pragma unroll 4
    for (int idx = d; idx < LL; idx += 256) {
        int t = g_t[b * LL + idx];
        if ((t >> 5) == c) slist[atomicAdd(&scount, 1)] = idx;
    }
    __syncthreads();
    int nq = scount;
    if (nq == 0) return;
    // build within-chunk prefixes on top of inter-chunk exclusive base
    pEV[d] = g_chEV[(b * NB + c) * DD + d];
    pV [d] = g_chV [(b * NB + c) * DD + d];
    if (csize) {
        float vr[32];
        #pragma unroll
        for (int i = 0; i < 32; i++)
            vr[i] = g_V[(size_t)(b * LL + sord[i]) * DD + d];
        #pragma unroll
        for (int i = 0; i < 32; i++) {
            pEV[(i + 1) * 256 + d] = fmaf(ev[i], vr[i], pEV[i * 256 + d]);
            pV [(i + 1) * 256 + d] = pV[i * 256 + d] + vr[i];
        }
    }
    if (d == 0) {
        float a = g_chE[b * NB + c];
        pe[0] = a;
        for (int i = 0; i < csize; i++) { a += ev[i]; pe[i + 1] = a; }
    }
    float TVd = g_chV[(b * NB + 128) * DD + d];
    __syncthreads();
    for (int p = 0; p < nq; p++) {
        int ql = slist[p];
        int qi = b * LL + ql;
        int t = g_t[qi];
        int rloc = t - c * 32;
        float E = expf(g_qs[qi]);
        float den = fmaf(E, pe[rloc], (float)(LL - t));
        float num = fmaf(E, pEV[rloc * 256 + d], TVd - pV[rloc * 256 + d]);
        out[(size_t)qi * DD + d] = num / den;
    }
}

// ---------------- launch: fork sort-chain onto a second stream under the GEMM ----------------
extern "C" void kernel_launch(void* const* d_in, const int* in_sizes, int n_in,
                              void* d_out, int out_size) {
    const float* x   = (const float*)d_in[0];
    const float* Wq  = (const float*)d_in[1];
    const float* Wk  = (const float*)d_in[2];
    const float* Wv  = (const float*)d_in[3];
    const float* w   = (const float*)d_in[4];
    const float* bm  = (const float*)d_in[5];
    float* out = (float*)d_out;

    static cudaStream_t s2 = nullptr;
    static cudaEvent_t ev_fork = nullptr, ev_join = nullptr;
    if (!s2) {
        cudaStreamCreateWithFlags(&s2, cudaStreamNonBlocking);
        cudaEventCreateWithFlags(&ev_fork, cudaEventDisableTiming);
        cudaEventCreateWithFlags(&ev_join, cudaEventDisableTiming);
        cudaFuncSetAttribute(k_gout, cudaFuncAttributeMaxDynamicSharedMemorySize,
                             2 * 33 * 256 * (int)sizeof(float));
    }

    // fork
    cudaEventRecord(ev_fork, 0);
    cudaStreamWaitEvent(s2, ev_fork, 0);

    // Leg B (stream s2): scalar/sort/rank chain — latency-bound, hides under GEMM
    k_uvec<<<2, 1024, 0, s2>>>(Wq, Wk, w);
    k_qk<<<BL / 64, 256, 0, s2>>>(x, bm);
    k_tsort<<<BL / 256, 256, 0, s2>>>();
    k_rank2<<<dim3(64, 16), 256, 0, s2>>>();
    k_ranksum<<<BL / 256, 256, 0, s2>>>();
    cudaEventRecord(ev_join, s2);

    // Leg A (default stream): the V projection GEMM
    k_vgemm<<<dim3(BL / 128, DD / 128), 256>>>(x, Wv);

    // join: chunksum needs both g_V (leg A) and g_ksort/g_ord (leg B)
    cudaStreamWaitEvent(0, ev_join, 0);
    k_chunksum<<<BB * 128, 256>>>();
    k_chunkscan<<<BB, 256>>>();
    k_gout<<<NBT, 256, 2 * 33 * 256 * sizeof(float)>>>(out);
}

// round 13
// speedup vs baseline: 2.6610x; 1.0203x over previous
#include <cuda_runtime.h>
#include <cuda_fp16.h>
#include <cstdint>

#define BB 4
#define LL 4096
#define DD 256
#define BL (BB*LL)
#define NB 129          // chunks per batch (128) + overflow bin (t=4096)
#define NBT (BB*NB)

// ---------------- static scratch ----------------
__device__ float g_V[BL*DD];
__device__ float g_uq[DD];
__device__ float g_uk[DD];
__device__ float g_qs[BL];
__device__ float g_ks[BL];
__device__ float g_ksort[BL];
__device__ int   g_ord[BL];
__device__ int   g_t[BL];
__device__ unsigned long long g_tk[BL];   // per-tile sorted packed keys
__device__ int   g_rpart[16*BL];          // per-tile k-rank partials
__device__ int   g_rpartq[16*BL];         // per-tile q-threshold partials
__device__ float g_chE[BB*NB];
__device__ float g_chEV[BB*NB*DD];
__device__ float g_chV[BB*NB*DD];

__device__ __forceinline__ uint32_t fmap(float f) {
    uint32_t u = __float_as_uint(f);
    return ((int)u < 0) ? ~u : (u | 0x80000000u);
}

// ---------------- uq = Wq^T w, uk = Wk^T w ----------------
__global__ void __launch_bounds__(1024) k_uvec(const float* __restrict__ Wq,
                                               const float* __restrict__ Wk,
                                               const float* __restrict__ w) {
    __shared__ float part[4][DD];
    const float* W = (blockIdx.x == 0) ? Wq : Wk;
    int d = threadIdx.x & 255, ec = threadIdx.x >> 8;
    float s = 0.f;
    #pragma unroll 8
    for (int e = ec * 64; e < ec * 64 + 64; e++)
        s = fmaf(W[e * DD + d], w[e], s);
    part[ec][d] = s;
    __syncthreads();
    if (ec == 0) {
        float r = part[0][d] + part[1][d] + part[2][d] + part[3][d];
        if (blockIdx.x == 0) g_uq[d] = r; else g_uk[d] = r;
    }
}

// ---------------- per-row scalar q/k ----------------
__global__ void __launch_bounds__(256) k_qk(const float* __restrict__ x,
                                            const float* __restrict__ bptr) {
    __shared__ float suq[DD], suk[DD];
    suq[threadIdx.x] = g_uq[threadIdx.x];
    suk[threadIdx.x] = g_uk[threadIdx.x];
    __syncthreads();
    int warp = threadIdx.x >> 5, lane = threadIdx.x & 31;
    float bias = bptr[0];
    #pragma unroll
    for (int r = 0; r < 8; r++) {
        int m = blockIdx.x * 64 + warp * 8 + r;
        const float* xr = x + (size_t)m * DD;
        float4 xa = *(const float4*)&xr[lane * 4];
        float4 xb = *(const float4*)&xr[128 + lane * 4];
        int da = lane * 4, db = 128 + lane * 4;
        float sq = xa.x * suq[da] + xa.y * suq[da+1] + xa.z * suq[da+2] + xa.w * suq[da+3]
                 + xb.x * suq[db] + xb.y * suq[db+1] + xb.z * suq[db+2] + xb.w * suq[db+3];
        float sk = xa.x * suk[da] + xa.y * suk[da+1] + xa.z * suk[da+2] + xa.w * suk[da+3]
                 + xb.x * suk[db] + xb.y * suk[db+1] + xb.z * suk[db+2] + xb.w * suk[db+3];
        #pragma unroll
        for (int o = 16; o; o >>= 1) {
            sq += __shfl_down_sync(0xffffffffu, sq, o);
            sk += __shfl_down_sync(0xffffffffu, sk, o);
        }
        if (lane == 0) { g_qs[m] = sq + bias; g_ks[m] = sk; }
    }
}

// ---------------- V = x @ Wv^T : mma.sync fp16 2-pass split ----------------
// x = Ah + Al (fp16), Wv = Bh + Bl (fp16). D ≈ Ah·Bh + Ah·Bl; dropped Al·B ~ 2^-12.
#define PITCH 36
__device__ __forceinline__ void mma_fp16(float* d, const uint32_t* a, const uint32_t* b) {
    asm volatile("mma.sync.aligned.m16n8k16.row.col.f32.f16.f16.f32 "
        "{%0,%1,%2,%3}, {%4,%5,%6,%7}, {%8,%9}, {%0,%1,%2,%3};"
        : "+f"(d[0]), "+f"(d[1]), "+f"(d[2]), "+f"(d[3])
        : "r"(a[0]), "r"(a[1]), "r"(a[2]), "r"(a[3]), "r"(b[0]), "r"(b[1]));
}

__global__ void __launch_bounds__(256) k_vgemm(const float* __restrict__ x,
                                               const float* __restrict__ Wv) {
    __shared__ __half sAh[128][PITCH];
    __shared__ __half sBh[128][PITCH], sBl[128][PITCH];
    int tid = threadIdx.x, wid = tid >> 5, lane = tid & 31;
    int g = lane >> 2, t4 = lane & 3;
    int wr = wid >> 2, wc = wid & 3;
    int m0 = blockIdx.x * 128, n0 = blockIdx.y * 128;

    float acc[4][4][4];
    #pragma unroll
    for (int mt = 0; mt < 4; mt++)
        #pragma unroll
        for (int nt = 0; nt < 4; nt++)
            #pragma unroll
            for (int e = 0; e < 4; e++) acc[mt][nt][e] = 0.f;

    for (int k0 = 0; k0 < DD; k0 += 32) {
        #pragma unroll
        for (int p = 0; p < 8; p++) {
            int s = p * 256 + tid;
            int row = (s & 1023) >> 3, kq = s & 7;
            if (s < 1024) {
                float4 v = *(const float4*)&x[(size_t)(m0 + row) * DD + k0 + kq * 4];
                __half2 h0 = __floats2half2_rn(v.x, v.y);
                __half2 h1 = __floats2half2_rn(v.z, v.w);
                *(uint2*)&sAh[row][kq * 4] =
                    make_uint2(*(uint32_t*)&h0, *(uint32_t*)&h1);
            } else {
                float4 v = *(const float4*)&Wv[(size_t)(n0 + row) * DD + k0 + kq * 4];
                __half2 h0 = __floats2half2_rn(v.x, v.y);
                __half2 h1 = __floats2half2_rn(v.z, v.w);
                __half2 l0 = __floats2half2_rn(v.x - __low2float(h0),
                                               v.y - __high2float(h0));
                __half2 l1 = __floats2half2_rn(v.z - __low2float(h1),
                                               v.w - __high2float(h1));
                *(uint2*)&sBh[row][kq * 4] =
                    make_uint2(*(uint32_t*)&h0, *(uint32_t*)&h1);
                *(uint2*)&sBl[row][kq * 4] =
                    make_uint2(*(uint32_t*)&l0, *(uint32_t*)&l1);
            }
        }
        __syncthreads();
        #pragma unroll
        for (int ks = 0; ks < 32; ks += 16) {
            uint32_t ah[4][4], bh[4][2], bl[4][2];
            #pragma unroll
            for (int mt = 0; mt < 4; mt++) {
                int rb = wr * 64 + mt * 16;
                int kc = ks + 2 * t4;
                ah[mt][0] = *(uint32_t*)&sAh[rb + g    ][kc];
                ah[mt][1] = *(uint32_t*)&sAh[rb + g + 8][kc];
                ah[mt][2] = *(uint32_t*)&sAh[rb + g    ][kc + 8];
                ah[mt][3] = *(uint32_t*)&sAh[rb + g + 8][kc + 8];
            }
            #pragma unroll
            for (int nt = 0; nt < 4; nt++) {
                int nb = wc * 32 + nt * 8;
                int kc = ks + 2 * t4;
                bh[nt][0] = *(uint32_t*)&sBh[nb + g][kc];
                bh[nt][1] = *(uint32_t*)&sBh[nb + g][kc + 8];
                bl[nt][0] = *(uint32_t*)&sBl[nb + g][kc];
                bl[nt][1] = *(uint32_t*)&sBl[nb + g][kc + 8];
            }
            #pragma unroll
            for (int mt = 0; mt < 4; mt++)
                #pragma unroll
                for (int nt = 0; nt < 4; nt++) {
                    mma_fp16(acc[mt][nt], ah[mt], bh[nt]);
                    mma_fp16(acc[mt][nt], ah[mt], bl[nt]);
                }
        }
        __syncthreads();
    }
    #pragma unroll
    for (int mt = 0; mt < 4; mt++)
        #pragma unroll
        for (int nt = 0; nt < 4; nt++) {
            int m = m0 + wr * 64 + mt * 16 + g;
            int n = n0 + wc * 32 + nt * 8 + 2 * t4;
            *(float2*)&g_V[(size_t)m * DD + n] =
                make_float2(acc[mt][nt][0], acc[mt][nt][1]);
            *(float2*)&g_V[(size_t)(m + 8) * DD + n] =
                make_float2(acc[mt][nt][2], acc[mt][nt][3]);
        }
}

// ---------------- sort 256-key tiles (bitonic, u64 packed keys) ----------------
__global__ void __launch_bounds__(256) k_tsort() {
    __shared__ unsigned long long sk[256];
    int base = blockIdx.x * 256;
    int tid = threadIdx.x;
    int jloc = (base + tid) & (LL - 1);
    sk[tid] = ((unsigned long long)fmap(g_ks[base + tid]) << 12) | (unsigned)jloc;
    __syncthreads();
    for (int k = 2; k <= 256; k <<= 1) {
        for (int j = k >> 1; j > 0; j >>= 1) {
            int ixj = tid ^ j;
            if (ixj > tid) {
                bool asc = ((tid & k) == 0);
                unsigned long long a = sk[tid], c = sk[ixj];
                if (asc ? (a > c) : (a < c)) { sk[tid] = c; sk[ixj] = a; }
            }
            __syncthreads();
        }
    }
    g_tk[base + tid] = sk[tid];
}

// ---------------- per-tile lower_bounds: 4-ary search (half the dependent LDS) ----------------
__device__ __forceinline__ int lb256(const unsigned long long* st, unsigned long long key) {
    if (st[255] < key) return 256;
    int pos = 0;
    #pragma unroll
    for (int w = 64; w >= 1; w >>= 2) {
        unsigned long long p1 = st[pos + w - 1];
        unsigned long long p2 = st[pos + 2 * w - 1];
        unsigned long long p3 = st[pos + 3 * w - 1];
        pos += w * ((int)(p1 < key) + (int)(p2 < key) + (int)(p3 < key));
    }
    return pos;
}

__global__ void __launch_bounds__(256) k_rank2() {
    __shared__ unsigned long long st[256];
    int tile = blockIdx.x;            // 0..63
    int batch = tile >> 4;
    int tid = threadIdx.x;
    st[tid] = g_tk[tile * 256 + tid];
    int j = batch * LL + blockIdx.y * 256 + tid;
    unsigned long long kj = ((unsigned long long)fmap(g_ks[j]) << 12)
                          | (unsigned)(j & (LL - 1));
    unsigned long long qj = ((unsigned long long)fmap(g_qs[j]) << 12);
    __syncthreads();
    g_rpart [(tile & 15) * BL + j] = lb256(st, kj);
    g_rpartq[(tile & 15) * BL + j] = lb256(st, qj);  // = #{k < q} in this tile
}

// ---------------- final rank: scatter sorted keys + threshold per query ----------------
__global__ void k_ranksum() {
    int j = blockIdx.x * 256 + threadIdx.x;
    int sumk = 0, sumq = 0;
    #pragma unroll
    for (int ic = 0; ic < 16; ic++) {
        sumk += g_rpart [ic * BL + j];
        sumq += g_rpartq[ic * BL + j];
    }
    int b = j >> 12;
    g_ksort[b * LL + sumk] = g_ks[j];
    g_ord[b * LL + sumk]   = j & (LL - 1);
    g_t[j] = sumq;
}

// ---------------- chunk sums (32-element chunks) ----------------
__global__ void __launch_bounds__(256) k_chunksum() {
    int bx = blockIdx.x;
    int b = bx >> 7, c = bx & 127;
    int d = threadIdx.x;
    __shared__ float ev[32];
    __shared__ int   sord[32];
    int base = b * LL + c * 32;
    if (d < 32) {
        float e = expf(-g_ksort[base + d]);
        ev[d] = e;
        sord[d] = g_ord[base + d];
        #pragma unroll
        for (int o = 16; o; o >>= 1) e += __shfl_down_sync(0xffffffffu, e, o);
        if (d == 0) g_chE[b * NB + c] = e;
    }
    __syncthreads();
    float sEV = 0.f, sV = 0.f;
    #pragma unroll 4
    for (int i = 0; i < 32; i++) {
        float v = g_V[(size_t)(b * LL + sord[i]) * DD + d];
        sEV = fmaf(ev[i], v, sEV);
        sV += v;
    }
    g_chEV[(b * NB + c) * DD + d] = sEV;
    g_chV [(b * NB + c) * DD + d] = sV;
}

// ---------------- exclusive scan over chunk sums (+ totals at idx 128) ----------------
__global__ void __launch_bounds__(256) k_chunkscan() {
    int b = blockIdx.x, d = threadIdx.x;
    float runEV = 0.f, runV = 0.f;
    #pragma unroll 8
    for (int c = 0; c < 128; c++) {
        int idx = (b * NB + c) * DD + d;
        float t1 = g_chEV[idx]; g_chEV[idx] = runEV; runEV += t1;
        float t2 = g_chV[idx];  g_chV[idx]  = runV;  runV  += t2;
    }
    g_chEV[(b * NB + 128) * DD + d] = runEV;
    g_chV [(b * NB + 128) * DD + d] = runV;
    if (d == 0) {
        float run = 0.f;
        #pragma unroll 8
        for (int c = 0; c < 128; c++) {
            float t = g_chE[b * NB + c]; g_chE[b * NB + c] = run; run += t;
        }
        g_chE[b * NB + 128] = run;
    }
}

// ---------------- grouped output: one block per (batch, chunk) bin ----------------
__global__ void __launch_bounds__(256) k_gout(float* __restrict__ out) {
    extern __shared__ float dsm[];
    float* pEV = dsm;               // [33][256]
    float* pV  = dsm + 33 * 256;    // [33][256]
    __shared__ float ev[32];
    __shared__ int   sord[32];
    __shared__ float pe[33];
    __shared__ int   slist[4096];
    __shared__ int   scount;
    int gbin = blockIdx.x;
    int b = gbin / NB, c = gbin - b * NB;
    int d = threadIdx.x;
    if (d == 0) scount = 0;
    int csize = (c < 128) ? 32 : 0;
    if (d < 32 && csize) {
        ev[d]   = expf(-g_ksort[b * LL + c * 32 + d]);
        sord[d] = g_ord[b * LL + c * 32 + d];
    }
    __syncthreads();
    // gather this bin's queries from g_t
    #pragma unroll 4
    for (int idx = d; idx < LL; idx += 256) {
        int t = g_t[b * LL + idx];
        if ((t >> 5) == c) slist[atomicAdd(&scount, 1)] = idx;
    }
    __syncthreads();
    int nq = scount;
    if (nq == 0) return;
    // build within-chunk prefixes on top of inter-chunk exclusive base
    pEV[d] = g_chEV[(b * NB + c) * DD + d];
    pV [d] = g_chV [(b * NB + c) * DD + d];
    if (csize) {
        float vr[32];
        #pragma unroll
        for (int i = 0; i < 32; i++)
            vr[i] = g_V[(size_t)(b * LL + sord[i]) * DD + d];
        #pragma unroll
        for (int i = 0; i < 32; i++) {
            pEV[(i + 1) * 256 + d] = fmaf(ev[i], vr[i], pEV[i * 256 + d]);
            pV [(i + 1) * 256 + d] = pV[i * 256 + d] + vr[i];
        }
    }
    if (d == 0) {
        float a = g_chE[b * NB + c];
        pe[0] = a;
        for (int i = 0; i < csize; i++) { a += ev[i]; pe[i + 1] = a; }
    }
    float TVd = g_chV[(b * NB + 128) * DD + d];
    __syncthreads();
    for (int p = 0; p < nq; p++) {
        int ql = slist[p];
        int qi = b * LL + ql;
        int t = g_t[qi];
        int rloc = t - c * 32;
        float E = expf(g_qs[qi]);
        float den = fmaf(E, pe[rloc], (float)(LL - t));
        float num = fmaf(E, pEV[rloc * 256 + d], TVd - pV[rloc * 256 + d]);
        out[(size_t)qi * DD + d] = num / den;
    }
}

// ---------------- launch: fork sort-chain onto a second stream under the GEMM ----------------
extern "C" void kernel_launch(void* const* d_in, const int* in_sizes, int n_in,
                              void* d_out, int out_size) {
    const float* x   = (const float*)d_in[0];
    const float* Wq  = (const float*)d_in[1];
    const float* Wk  = (const float*)d_in[2];
    const float* Wv  = (const float*)d_in[3];
    const float* w   = (const float*)d_in[4];
    const float* bm  = (const float*)d_in[5];
    float* out = (float*)d_out;

    static cudaStream_t s2 = nullptr;
    static cudaEvent_t ev_fork = nullptr, ev_join = nullptr;
    if (!s2) {
        cudaStreamCreateWithFlags(&s2, cudaStreamNonBlocking);
        cudaEventCreateWithFlags(&ev_fork, cudaEventDisableTiming);
        cudaEventCreateWithFlags(&ev_join, cudaEventDisableTiming);
        cudaFuncSetAttribute(k_gout, cudaFuncAttributeMaxDynamicSharedMemorySize,
                             2 * 33 * 256 * (int)sizeof(float));
    }

    // fork
    cudaEventRecord(ev_fork, 0);
    cudaStreamWaitEvent(s2, ev_fork, 0);

    // Leg B (stream s2): scalar/sort/rank chain — latency-bound, hides under GEMM
    k_uvec<<<2, 1024, 0, s2>>>(Wq, Wk, w);
    k_qk<<<BL / 64, 256, 0, s2>>>(x, bm);
    k_tsort<<<BL / 256, 256, 0, s2>>>();
    k_rank2<<<dim3(64, 16), 256, 0, s2>>>();
    k_ranksum<<<BL / 256, 256, 0, s2>>>();
    cudaEventRecord(ev_join, s2);

    // Leg A (default stream): the V projection GEMM
    k_vgemm<<<dim3(BL / 128, DD / 128), 256>>>(x, Wv);

    // join: chunksum needs both g_V (leg A) and g_ksort/g_ord (leg B)
    cudaStreamWaitEvent(0, ev_join, 0);
    k_chunksum<<<BB * 128, 256>>>();
    k_chunkscan<<<BB, 256>>>();
    k_gout<<<NBT, 256, 2 * 33 * 256 * sizeof(float)>>>(out);
}